// round 6
// baseline (speedup 1.0000x reference)
#include <cuda_runtime.h>
#include <math.h>
#include <stdint.h>

// Problem constants
#define S_LEN   2048
#define NH      16
#define HD      64
#define BH_TOT  32          // B * NH
#define M_ROWS  4096        // B * S
#define H_DIM   1024
#define QKV_N   3072

// -------- scratch (device globals: no allocation allowed) --------
__device__ float g_qkv[(size_t)M_ROWS * QKV_N];          // fp32 QKV GEMM out
__device__ float g_q[(size_t)BH_TOT * S_LEN * HD];       // tf32-rounded
__device__ float g_k[(size_t)BH_TOT * S_LEN * HD];       // tf32-rounded
__device__ float g_v[(size_t)BH_TOT * S_LEN * HD];       // tf32-rounded
__device__ float g_attn[(size_t)M_ROWS * H_DIM];         // tf32-rounded O
__device__ float g_xa[(size_t)M_ROWS * H_DIM];           // tf32-rounded x
__device__ float g_wqkv[(size_t)QKV_N * H_DIM];          // tf32-rounded W_qkv
__device__ float g_wproj[(size_t)H_DIM * H_DIM];         // tf32-rounded W_proj
__device__ float g_cos[S_LEN * 32];
__device__ float g_sin[S_LEN * 32];

// ================= small helpers =================
__device__ __forceinline__ uint32_t f2tf32(float x) {
    uint32_t r; asm("cvt.rna.tf32.f32 %0, %1;" : "=r"(r) : "f"(x)); return r;
}
__device__ __forceinline__ float f2tf32f(float x) { return __uint_as_float(f2tf32(x)); }

__device__ __forceinline__ void mma8(float d[4], const uint32_t a[4], const uint32_t b[2]) {
    asm volatile("mma.sync.aligned.m16n8k8.row.col.f32.tf32.tf32.f32 "
                 "{%0,%1,%2,%3}, {%4,%5,%6,%7}, {%8,%9}, {%0,%1,%2,%3};\n"
                 : "+f"(d[0]), "+f"(d[1]), "+f"(d[2]), "+f"(d[3])
                 : "r"(a[0]), "r"(a[1]), "r"(a[2]), "r"(a[3]),
                   "r"(b[0]), "r"(b[1]));
}

__device__ __forceinline__ void cp16(uint32_t s, const void* g) {
    asm volatile("cp.async.cg.shared.global [%0], [%1], 16;" :: "r"(s), "l"(g));
}
__device__ __forceinline__ void cp_commit() { asm volatile("cp.async.commit_group;"); }
template<int N> __device__ __forceinline__ void cp_wait() {
    asm volatile("cp.async.wait_group %0;" :: "n"(N));
}

// pure-FMA exp2 (degree-6 Taylor on |f|<=0.5; rel err ~1e-7). No MUFU.
__device__ __forceinline__ float fexp2(float x) {
    x = fmaxf(x, -100.f);
    float i = rintf(x);
    float f = x - i;
    float p = fmaf(f, 1.54035304e-4f, 1.33335581e-3f);
    p = fmaf(p, f, 9.61812911e-3f);
    p = fmaf(p, f, 5.55041087e-2f);
    p = fmaf(p, f, 2.40226507e-1f);
    p = fmaf(p, f, 6.93147181e-1f);
    p = fmaf(p, f, 1.0f);
    return __int_as_float(__float_as_int(p) + (((int)i) << 23));
}

// C-fragment (m16n8 f32) -> A-fragment (m16k8 tf32) of the SAME 16x8 tile.
__device__ __forceinline__ void cfrag_to_afrag(const float c[4], uint32_t a[4]) {
    int t = threadIdx.x & 31;
    int src0 = (t & 28) | ((t & 3) >> 1);
    int src2 = src0 + 2;
    float x00 = __shfl_sync(0xffffffffu, c[0], src0);
    float x01 = __shfl_sync(0xffffffffu, c[1], src0);
    float x10 = __shfl_sync(0xffffffffu, c[2], src0);
    float x11 = __shfl_sync(0xffffffffu, c[3], src0);
    float y00 = __shfl_sync(0xffffffffu, c[0], src2);
    float y01 = __shfl_sync(0xffffffffu, c[1], src2);
    float y10 = __shfl_sync(0xffffffffu, c[2], src2);
    float y11 = __shfl_sync(0xffffffffu, c[3], src2);
    bool odd = t & 1;
    a[0] = f2tf32(odd ? x01 : x00);
    a[1] = f2tf32(odd ? x11 : x10);
    a[2] = f2tf32(odd ? y01 : y00);
    a[3] = f2tf32(odd ? y11 : y10);
}

// ================= RoPE tables =================
__global__ void init_rope_tables() {
    int idx = blockIdx.x * blockDim.x + threadIdx.x;
    if (idx >= S_LEN * 32) return;
    int s = idx >> 5;
    int j = idx & 31;
    double invf = exp(-log(10000.0) * (double)j / 32.0);
    double ang  = (double)s * invf;
    g_cos[idx] = (float)cos(ang);
    g_sin[idx] = (float)sin(ang);
}

// ================= tf32 pre-rounding of inputs =================
__global__ void cvt_x(const float* __restrict__ in) {
    int i = (blockIdx.x * blockDim.x + threadIdx.x) * 4;
    if (i >= M_ROWS * H_DIM) return;
    float4 v = *(const float4*)(in + i);
    v.x = f2tf32f(v.x); v.y = f2tf32f(v.y); v.z = f2tf32f(v.z); v.w = f2tf32f(v.w);
    *(float4*)(g_xa + i) = v;
}
__global__ void cvt_wqkv(const float* __restrict__ in) {
    int i = (blockIdx.x * blockDim.x + threadIdx.x) * 4;
    if (i >= QKV_N * H_DIM) return;
    float4 v = *(const float4*)(in + i);
    v.x = f2tf32f(v.x); v.y = f2tf32f(v.y); v.z = f2tf32f(v.z); v.w = f2tf32f(v.w);
    *(float4*)(g_wqkv + i) = v;
}
__global__ void cvt_wproj(const float* __restrict__ in) {
    int i = (blockIdx.x * blockDim.x + threadIdx.x) * 4;
    if (i >= H_DIM * H_DIM) return;
    float4 v = *(const float4*)(in + i);
    v.x = f2tf32f(v.x); v.y = f2tf32f(v.y); v.z = f2tf32f(v.z); v.w = f2tf32f(v.w);
    *(float4*)(g_wproj + i) = v;
}

// ================= tf32 GEMM: C[M][N] = A[M][K] * B[N][K]^T =================
// Inputs A,B hold tf32-rounded bit patterns. CTA 128x128, k-chunk 32,
// 8 warps (4x2), warp tile 32x64, 2-stage cp.async pipeline.
// smem: As[2][128][36] + Bs[2][128][36] = 73728 B (stride 36 == 4 mod 32
// makes every fragment LDS hit 32 distinct banks).
__device__ __forceinline__ void gemm_body(
    const float* __restrict__ A, const float* __restrict__ B,
    float* __restrict__ C, int M, int N, int K)
{
    extern __shared__ float sm[];
    float* As = sm;            // 2 * 128*36 floats
    float* Bs = sm + 2 * 128 * 36;

    const int tid = threadIdx.x;
    const int bm = blockIdx.y * 128, bn = blockIdx.x * 128;

    const int lr = tid >> 1;           // 0..127 row in tile
    const int k0 = (tid & 1) << 4;     // 0 or 16
    const float* Ag = A + (size_t)(bm + lr) * K + k0;
    const float* Bg = B + (size_t)(bn + lr) * K + k0;
    uint32_t sA = (uint32_t)__cvta_generic_to_shared(As) + (lr * 36 + k0) * 4;
    uint32_t sB = (uint32_t)__cvta_generic_to_shared(Bs) + (lr * 36 + k0) * 4;
    const uint32_t bufB = 128 * 36 * 4;

    auto issue = [&](int chunk) {
        int buf = chunk & 1;
        const float* a = Ag + chunk * 32;
        const float* b = Bg + chunk * 32;
        uint32_t da = sA + buf * bufB;
        uint32_t db = sB + buf * bufB;
#pragma unroll
        for (int j = 0; j < 4; ++j) { cp16(da + j * 16, a + j * 4); cp16(db + j * 16, b + j * 4); }
        cp_commit();
    };

    issue(0);

    const int warp = tid >> 5, lane = tid & 31;
    const int g = lane >> 2, q4 = lane & 3;
    const int wm = (warp >> 1) * 32;
    const int wn = (warp & 1) * 64;

    float acc[2][8][4] = {};
    const int nChunks = K >> 5;
    for (int it = 0; it < nChunks; ++it) {
        if (it + 1 < nChunks) { issue(it + 1); cp_wait<1>(); }
        else                  { cp_wait<0>(); }
        __syncthreads();
        const float* Ab = As + (it & 1) * (128 * 36);
        const float* Bb = Bs + (it & 1) * (128 * 36);
#pragma unroll
        for (int kk = 0; kk < 4; ++kk) {
            uint32_t af[2][4];
#pragma unroll
            for (int mi = 0; mi < 2; ++mi) {
                const float* base = Ab + (wm + mi * 16 + g) * 36 + kk * 8 + q4;
                af[mi][0] = __float_as_uint(base[0]);
                af[mi][1] = __float_as_uint(base[8 * 36]);
                af[mi][2] = __float_as_uint(base[4]);
                af[mi][3] = __float_as_uint(base[8 * 36 + 4]);
            }
#pragma unroll
            for (int j = 0; j < 8; ++j) {
                uint32_t bf[2];
                const float* base = Bb + (wn + j * 8 + g) * 36 + kk * 8 + q4;
                bf[0] = __float_as_uint(base[0]);
                bf[1] = __float_as_uint(base[4]);
                mma8(acc[0][j], af[0], bf);
                mma8(acc[1][j], af[1], bf);
            }
        }
        __syncthreads();
    }

#pragma unroll
    for (int mi = 0; mi < 2; ++mi)
#pragma unroll
        for (int r = 0; r < 2; ++r) {
            int row = bm + wm + mi * 16 + g + r * 8;
            float* Cp = C + (size_t)row * N + bn + wn;
#pragma unroll
            for (int j = 0; j < 8; ++j) {
                float2 v = make_float2(acc[mi][j][r * 2], acc[mi][j][r * 2 + 1]);
                *(float2*)(Cp + j * 8 + q4 * 2) = v;
            }
        }
}

__global__ void __launch_bounds__(256) gemm_qkv(const float* __restrict__ unused) {
    gemm_body(g_xa, g_wqkv, g_qkv, M_ROWS, QKV_N, H_DIM);
}
__global__ void __launch_bounds__(256) gemm_proj(float* __restrict__ out) {
    gemm_body(g_attn, g_wproj, out, M_ROWS, H_DIM, H_DIM);
}

// ================= RoPE + permute (writes tf32-rounded) =================
__global__ void __launch_bounds__(256) rope_permute() {
    int idx = blockIdx.x * blockDim.x + threadIdx.x;
    if (idx >= (3 << 22)) return;
    const int d      = idx & 63;
    const int s      = (idx >> 6) & 2047;
    const int bh     = (idx >> 17) & 31;
    const int region = idx >> 22;                       // 0=q 1=k 2=v
    const int b = bh >> 4, h = bh & 15;
    const int m = b * S_LEN + s;

    const float* src = g_qkv + (size_t)m * QKV_N + region * H_DIM + h * HD;
    float val;
    if (region == 2 || d >= 32) {
        val = src[d];
    } else {
        const float c  = g_cos[s * 32 + d];
        const float sn = g_sin[s * 32 + d];
        const float x0 = src[d];
        const float xr = (d < 16) ? -src[d + 16] : src[d - 16];
        val = x0 * c + xr * sn;
    }
    float* dst = (region == 0) ? g_q : (region == 1) ? g_k : g_v;
    dst[((size_t)bh * S_LEN + s) * HD + d] = f2tf32f(val);
}

// ================= Flash attention, tf32 mma + FMA-only softmax =========
// CTA: 128 Q rows x bh. 8 warps; warp owns 16 Q rows (one m16 tile).
// KV chunks of 64, 2-stage cp.async.  smem strides: Q/K 68 (==4 mod 32),
// V 72 (==8 mod 32) -> conflict-free fragment loads.
// smem = (128*68 + 2*64*68 + 2*64*72) * 4 = 106496 B.
__global__ void __launch_bounds__(256) flash_attn() {
    extern __shared__ float sm[];
    float* Qs = sm;                       // 128*68
    float* Ks = sm + 8704;                // 2*64*68
    float* Vs = sm + 8704 + 8704;         // 2*64*72

    const int tid = threadIdx.x;
    const int warp = tid >> 5, lane = tid & 31;
    const int g = lane >> 2, q4 = lane & 3;
    const int q0 = blockIdx.x * 128;
    const int bh = blockIdx.y;

    const float* Qg = g_q + ((size_t)bh * S_LEN + q0) * HD;
    const float* Kb = g_k + (size_t)bh * S_LEN * HD;
    const float* Vb = g_v + (size_t)bh * S_LEN * HD;

    // Q load (part of cp.async group 0)
    {
        int qr = tid >> 1, d0 = (tid & 1) * 32;
        uint32_t dst = (uint32_t)__cvta_generic_to_shared(Qs) + (qr * 68 + d0) * 4;
        const float* src = Qg + qr * 64 + d0;
#pragma unroll
        for (int j = 0; j < 8; ++j) cp16(dst + j * 16, src + j * 4);
    }
    const int kc = tid >> 2, kd = (tid & 3) * 16;
    uint32_t sK = (uint32_t)__cvta_generic_to_shared(Ks) + (kc * 68 + kd) * 4;
    uint32_t sV = (uint32_t)__cvta_generic_to_shared(Vs) + (kc * 72 + kd) * 4;
    auto issueKV = [&](int chunk) {
        int buf = chunk & 1;
        const float* kg = Kb + (size_t)chunk * 64 * 64 + kc * 64 + kd;
        const float* vg = Vb + (size_t)chunk * 64 * 64 + kc * 64 + kd;
        uint32_t dk = sK + buf * (64 * 68 * 4);
        uint32_t dv = sV + buf * (64 * 72 * 4);
#pragma unroll
        for (int j = 0; j < 4; ++j) { cp16(dk + j * 16, kg + j * 4); cp16(dv + j * 16, vg + j * 4); }
        cp_commit();
    };
    issueKV(0);   // group 0 = Q + K0 + V0

    const int wq = warp * 16;
    uint32_t qf[8][4];
    float o[8][4] = {};
    float m0 = -1e30f, m1 = -1e30f, l0 = 0.f, l1 = 0.f;
    const float CE = 0.125f * 1.44269504088896f;   // scale * log2(e)

    const int nChunks = S_LEN / 64;
    for (int it = 0; it < nChunks; ++it) {
        if (it + 1 < nChunks) { issueKV(it + 1); cp_wait<1>(); }
        else                  { cp_wait<0>(); }
        __syncthreads();
        if (it == 0) {
#pragma unroll
            for (int kk = 0; kk < 8; ++kk) {
                const float* base = Qs + (wq + g) * 68 + kk * 8 + q4;
                qf[kk][0] = __float_as_uint(base[0]);
                qf[kk][1] = __float_as_uint(base[8 * 68]);
                qf[kk][2] = __float_as_uint(base[4]);
                qf[kk][3] = __float_as_uint(base[8 * 68 + 4]);
            }
        }
        const float* Kc = Ks + (it & 1) * (64 * 68);
        const float* Vc = Vs + (it & 1) * (64 * 72);

        // ---- scores: S(16x64) = Q Kt ----
        float s[8][4] = {};
#pragma unroll
        for (int kk = 0; kk < 8; ++kk) {
#pragma unroll
            for (int nt = 0; nt < 8; ++nt) {
                uint32_t bf[2];
                const float* base = Kc + (nt * 8 + g) * 68 + kk * 8 + q4;
                bf[0] = __float_as_uint(base[0]);
                bf[1] = __float_as_uint(base[4]);
                mma8(s[nt], qf[kk], bf);
            }
        }

        // ---- online softmax (raw scores; 1/8 scale folded into CE) ----
        float mx0 = -1e30f, mx1 = -1e30f;
#pragma unroll
        for (int nt = 0; nt < 8; ++nt) {
            mx0 = fmaxf(mx0, fmaxf(s[nt][0], s[nt][1]));
            mx1 = fmaxf(mx1, fmaxf(s[nt][2], s[nt][3]));
        }
        mx0 = fmaxf(mx0, __shfl_xor_sync(0xffffffffu, mx0, 1));
        mx0 = fmaxf(mx0, __shfl_xor_sync(0xffffffffu, mx0, 2));
        mx1 = fmaxf(mx1, __shfl_xor_sync(0xffffffffu, mx1, 1));
        mx1 = fmaxf(mx1, __shfl_xor_sync(0xffffffffu, mx1, 2));

        float mn0 = fmaxf(m0, mx0), mn1 = fmaxf(m1, mx1);
        float al0 = fexp2(CE * (m0 - mn0)), al1 = fexp2(CE * (m1 - mn1));
        m0 = mn0; m1 = mn1;

        float sum0 = 0.f, sum1 = 0.f;
#pragma unroll
        for (int nt = 0; nt < 8; ++nt) {
            s[nt][0] = fexp2(CE * (s[nt][0] - m0));
            s[nt][1] = fexp2(CE * (s[nt][1] - m0));
            s[nt][2] = fexp2(CE * (s[nt][2] - m1));
            s[nt][3] = fexp2(CE * (s[nt][3] - m1));
            sum0 += s[nt][0] + s[nt][1];
            sum1 += s[nt][2] + s[nt][3];
        }
        sum0 += __shfl_xor_sync(0xffffffffu, sum0, 1);
        sum0 += __shfl_xor_sync(0xffffffffu, sum0, 2);
        sum1 += __shfl_xor_sync(0xffffffffu, sum1, 1);
        sum1 += __shfl_xor_sync(0xffffffffu, sum1, 2);
        l0 = l0 * al0 + sum0;
        l1 = l1 * al1 + sum1;
#pragma unroll
        for (int dt = 0; dt < 8; ++dt) {
            o[dt][0] *= al0; o[dt][1] *= al0; o[dt][2] *= al1; o[dt][3] *= al1;
        }

        // ---- PV: O += P V ----
#pragma unroll
        for (int kt = 0; kt < 8; ++kt) {
            uint32_t pa[4];
            cfrag_to_afrag(s[kt], pa);
#pragma unroll
            for (int dt = 0; dt < 8; ++dt) {
                uint32_t bf[2];
                const float* base = Vc + (kt * 8 + q4) * 72 + dt * 8 + g;
                bf[0] = __float_as_uint(base[0]);
                bf[1] = __float_as_uint(base[4 * 72]);
                mma8(o[dt], pa, bf);
            }
        }
        __syncthreads();
    }

    // ---- epilogue: normalize + tf32-round into [m][h*64+d] for proj ----
    const float inv0 = 1.0f / l0, inv1 = 1.0f / l1;
    const int b = bh >> 4, h = bh & 15;
    const int r0 = q0 + wq + g, r1 = r0 + 8;
    float* O0 = g_attn + ((size_t)(b * S_LEN) + r0) * H_DIM + h * HD;
    float* O1 = g_attn + ((size_t)(b * S_LEN) + r1) * H_DIM + h * HD;
#pragma unroll
    for (int dt = 0; dt < 8; ++dt) {
        int col = dt * 8 + q4 * 2;
        *(float2*)(O0 + col) = make_float2(f2tf32f(o[dt][0] * inv0), f2tf32f(o[dt][1] * inv0));
        *(float2*)(O1 + col) = make_float2(f2tf32f(o[dt][2] * inv1), f2tf32f(o[dt][3] * inv1));
    }
}

// ================= launch =================
extern "C" void kernel_launch(void* const* d_in, const int* in_sizes, int n_in,
                              void* d_out, int out_size)
{
    const float* x     = (const float*)d_in[0];   // [2,2048,1024]
    const float* Wqkv  = (const float*)d_in[1];   // [3072,1024]
    const float* Wproj = (const float*)d_in[2];   // [1024,1024]
    float* out = (float*)d_out;                   // [2,2048,1024]

    const int GEMM_SMEM  = 2 * 2 * 128 * 36 * 4;            // 73728
    const int FLASH_SMEM = (128 * 68 + 2 * 64 * 68 + 2 * 64 * 72) * 4; // 106496
    cudaFuncSetAttribute(gemm_qkv,  cudaFuncAttributeMaxDynamicSharedMemorySize, GEMM_SMEM);
    cudaFuncSetAttribute(gemm_proj, cudaFuncAttributeMaxDynamicSharedMemorySize, GEMM_SMEM);
    cudaFuncSetAttribute(flash_attn, cudaFuncAttributeMaxDynamicSharedMemorySize, FLASH_SMEM);

    init_rope_tables<<<(S_LEN * 32 + 255) / 256, 256>>>();
    cvt_x<<<(M_ROWS * H_DIM / 4 + 255) / 256, 256>>>(x);
    cvt_wqkv<<<(QKV_N * H_DIM / 4 + 255) / 256, 256>>>(Wqkv);
    cvt_wproj<<<(H_DIM * H_DIM / 4 + 255) / 256, 256>>>(Wproj);

    gemm_qkv<<<dim3(QKV_N / 128, M_ROWS / 128), 256, GEMM_SMEM>>>(nullptr);
    rope_permute<<<(3 << 22) / 256, 256>>>();
    flash_attn<<<dim3(S_LEN / 128, BH_TOT), 256, FLASH_SMEM>>>();
    gemm_proj<<<dim3(H_DIM / 128, M_ROWS / 128), 256, GEMM_SMEM>>>(out);
}

// round 12
// speedup vs baseline: 1.3885x; 1.3885x over previous
#include <cuda_runtime.h>
#include <math.h>
#include <stdint.h>

// Problem constants
#define S_LEN   2048
#define NH      16
#define HD      64
#define BH_TOT  32          // B * NH
#define M_ROWS  4096        // B * S
#define H_DIM   1024
#define QKV_N   3072

// Contraction-dim permutation (groups of 8):
//   storage order [k0,k4,k1,k5,k2,k6,k3,k7];
//   position p holds true k = (p>>1) + ((p&1)<<2);
//   true k stored at position ((k&3)<<1) | (k>>2).
// Applied to: x/Wqkv/Wproj K-dims, Q/K head-dims, g_attn columns.
// mma fragment k-pair (q4, q4+4) becomes adjacent -> float2 loads.

// -------- scratch (device globals: no allocation allowed) --------
__device__ float g_qkv[(size_t)M_ROWS * QKV_N];          // fp32, TRUE col order
__device__ float g_q[(size_t)BH_TOT * S_LEN * HD];       // tf32, d-permuted
__device__ float g_k[(size_t)BH_TOT * S_LEN * HD];       // tf32, d-permuted
__device__ float g_v[(size_t)BH_TOT * S_LEN * HD];       // tf32, TRUE order
__device__ float g_attn[(size_t)M_ROWS * H_DIM];         // tf32, col-permuted
__device__ float g_xa[(size_t)M_ROWS * H_DIM];           // tf32, k-permuted
__device__ float g_wqkv[(size_t)QKV_N * H_DIM];          // tf32, k-permuted
__device__ float g_wproj[(size_t)H_DIM * H_DIM];         // tf32, k-permuted
__device__ float g_cos[S_LEN * 32];
__device__ float g_sin[S_LEN * 32];

// ================= small helpers =================
__device__ __forceinline__ uint32_t f2tf32(float x) {
    uint32_t r; asm("cvt.rna.tf32.f32 %0, %1;" : "=r"(r) : "f"(x)); return r;
}
__device__ __forceinline__ float f2tf32f(float x) { return __uint_as_float(f2tf32(x)); }

__device__ __forceinline__ void mma8(float d[4], const uint32_t a[4], const uint32_t b[2]) {
    asm volatile("mma.sync.aligned.m16n8k8.row.col.f32.tf32.tf32.f32 "
                 "{%0,%1,%2,%3}, {%4,%5,%6,%7}, {%8,%9}, {%0,%1,%2,%3};\n"
                 : "+f"(d[0]), "+f"(d[1]), "+f"(d[2]), "+f"(d[3])
                 : "r"(a[0]), "r"(a[1]), "r"(a[2]), "r"(a[3]),
                   "r"(b[0]), "r"(b[1]));
}

__device__ __forceinline__ void cp16(uint32_t s, const void* g) {
    asm volatile("cp.async.cg.shared.global [%0], [%1], 16;" :: "r"(s), "l"(g));
}
__device__ __forceinline__ void cp_commit() { asm volatile("cp.async.commit_group;"); }
template<int N> __device__ __forceinline__ void cp_wait() {
    asm volatile("cp.async.wait_group %0;" :: "n"(N));
}

// pure-FMA exp2 (degree-6; rel err ~1e-7). No MUFU.
__device__ __forceinline__ float fexp2(float x) {
    x = fmaxf(x, -100.f);
    float i = rintf(x);
    float f = x - i;
    float p = fmaf(f, 1.54035304e-4f, 1.33335581e-3f);
    p = fmaf(p, f, 9.61812911e-3f);
    p = fmaf(p, f, 5.55041087e-2f);
    p = fmaf(p, f, 2.40226507e-1f);
    p = fmaf(p, f, 6.93147181e-1f);
    p = fmaf(p, f, 1.0f);
    return __int_as_float(__float_as_int(p) + (((int)i) << 23));
}

// C-fragment (m16n8 f32) -> A-fragment (m16k8 tf32) of the SAME 16x8 tile.
__device__ __forceinline__ void cfrag_to_afrag(const float c[4], uint32_t a[4]) {
    int t = threadIdx.x & 31;
    int src0 = (t & 28) | ((t & 3) >> 1);
    int src2 = src0 + 2;
    float x00 = __shfl_sync(0xffffffffu, c[0], src0);
    float x01 = __shfl_sync(0xffffffffu, c[1], src0);
    float x10 = __shfl_sync(0xffffffffu, c[2], src0);
    float x11 = __shfl_sync(0xffffffffu, c[3], src0);
    float y00 = __shfl_sync(0xffffffffu, c[0], src2);
    float y01 = __shfl_sync(0xffffffffu, c[1], src2);
    float y10 = __shfl_sync(0xffffffffu, c[2], src2);
    float y11 = __shfl_sync(0xffffffffu, c[3], src2);
    bool odd = t & 1;
    a[0] = f2tf32(odd ? x01 : x00);
    a[1] = f2tf32(odd ? x11 : x10);
    a[2] = f2tf32(odd ? y01 : y00);
    a[3] = f2tf32(odd ? y11 : y10);
}

// ================= RoPE tables =================
__global__ void init_rope_tables() {
    int idx = blockIdx.x * blockDim.x + threadIdx.x;
    if (idx >= S_LEN * 32) return;
    int s = idx >> 5;
    int j = idx & 31;
    double invf = exp(-log(10000.0) * (double)j / 32.0);
    double ang  = (double)s * invf;
    g_cos[idx] = (float)cos(ang);
    g_sin[idx] = (float)sin(ang);
}

// ======== tf32 round + k-permute =====================================
// NOTE: destination globals are bound INSIDE device code via wrappers —
// passing a __device__ array address from host is invalid (R6-R9 bug).
__device__ __forceinline__ void cvt_perm8_body(
    const float* __restrict__ in, float* __restrict__ out, int n8)
{
    int gi = blockIdx.x * blockDim.x + threadIdx.x;
    if (gi >= n8) return;
    const float4* p = (const float4*)(in + (size_t)gi * 8);
    float4 a = p[0], b = p[1];          // a = k0..3, b = k4..7
    float4 o0 = make_float4(f2tf32f(a.x), f2tf32f(b.x), f2tf32f(a.y), f2tf32f(b.y));
    float4 o1 = make_float4(f2tf32f(a.z), f2tf32f(b.z), f2tf32f(a.w), f2tf32f(b.w));
    float4* q = (float4*)(out + (size_t)gi * 8);
    q[0] = o0; q[1] = o1;
}
__global__ void __launch_bounds__(256) cvt_x(const float* __restrict__ in) {
    cvt_perm8_body(in, g_xa, M_ROWS * H_DIM / 8);
}
__global__ void __launch_bounds__(256) cvt_wqkv(const float* __restrict__ in) {
    cvt_perm8_body(in, g_wqkv, QKV_N * H_DIM / 8);
}
__global__ void __launch_bounds__(256) cvt_wproj(const float* __restrict__ in) {
    cvt_perm8_body(in, g_wproj, H_DIM * H_DIM / 8);
}

// ================= tf32 GEMM: C[M][N] = A[M][K] * B[N][K]^T ===============
// A,B tf32-rounded AND k-permuted; C written in TRUE n-order.
// CTA 128x128, k-chunk 32, 8 warps (4x2), warp 32x64, 2-stage cp.async.
// smem 73728 B; stride 36 (==4 mod 32) keeps float2 frag loads conflict-free.
__device__ __forceinline__ void gemm_body(
    const float* __restrict__ A, const float* __restrict__ B,
    float* __restrict__ C, int M, int N, int K)
{
    extern __shared__ float sm[];
    float* As = sm;
    float* Bs = sm + 2 * 128 * 36;

    const int tid = threadIdx.x;
    const int bm = blockIdx.y * 128, bn = blockIdx.x * 128;

    const int lr = tid >> 1;
    const int k0 = (tid & 1) << 4;
    const float* Ag = A + (size_t)(bm + lr) * K + k0;
    const float* Bg = B + (size_t)(bn + lr) * K + k0;
    uint32_t sA = (uint32_t)__cvta_generic_to_shared(As) + (lr * 36 + k0) * 4;
    uint32_t sB = (uint32_t)__cvta_generic_to_shared(Bs) + (lr * 36 + k0) * 4;
    const uint32_t bufB = 128 * 36 * 4;

    auto issue = [&](int chunk) {
        int buf = chunk & 1;
        const float* a = Ag + chunk * 32;
        const float* b = Bg + chunk * 32;
        uint32_t da = sA + buf * bufB;
        uint32_t db = sB + buf * bufB;
#pragma unroll
        for (int j = 0; j < 4; ++j) { cp16(da + j * 16, a + j * 4); cp16(db + j * 16, b + j * 4); }
        cp_commit();
    };

    issue(0);

    const int warp = tid >> 5, lane = tid & 31;
    const int g = lane >> 2, q4 = lane & 3;
    const int wm = (warp >> 1) * 32;
    const int wn = (warp & 1) * 64;

    float acc[2][8][4] = {};
    const int nChunks = K >> 5;
    for (int it = 0; it < nChunks; ++it) {
        if (it + 1 < nChunks) { issue(it + 1); cp_wait<1>(); }
        else                  { cp_wait<0>(); }
        __syncthreads();
        const float* Ab = As + (it & 1) * (128 * 36);
        const float* Bb = Bs + (it & 1) * (128 * 36);
#pragma unroll
        for (int kk = 0; kk < 4; ++kk) {
            uint32_t af[2][4];
#pragma unroll
            for (int mi = 0; mi < 2; ++mi) {
                const float* base = Ab + (wm + mi * 16 + g) * 36 + kk * 8 + 2 * q4;
                float2 lo = *(const float2*)base;            // true k = q4
                float2 hi = *(const float2*)(base + 8 * 36); // rows +8
                af[mi][0] = __float_as_uint(lo.x);
                af[mi][1] = __float_as_uint(hi.x);
                af[mi][2] = __float_as_uint(lo.y);           // true k = q4+4
                af[mi][3] = __float_as_uint(hi.y);
            }
#pragma unroll
            for (int j = 0; j < 8; ++j) {
                float2 bb = *(const float2*)(Bb + (wn + j * 8 + g) * 36 + kk * 8 + 2 * q4);
                uint32_t bf[2] = { __float_as_uint(bb.x), __float_as_uint(bb.y) };
                mma8(acc[0][j], af[0], bf);
                mma8(acc[1][j], af[1], bf);
            }
        }
        __syncthreads();
    }

#pragma unroll
    for (int mi = 0; mi < 2; ++mi)
#pragma unroll
        for (int r = 0; r < 2; ++r) {
            int row = bm + wm + mi * 16 + g + r * 8;
            float* Cp = C + (size_t)row * N + bn + wn;
#pragma unroll
            for (int j = 0; j < 8; ++j) {
                float2 v = make_float2(acc[mi][j][r * 2], acc[mi][j][r * 2 + 1]);
                *(float2*)(Cp + j * 8 + q4 * 2) = v;
            }
        }
}

__global__ void __launch_bounds__(256) gemm_qkv() {
    gemm_body(g_xa, g_wqkv, g_qkv, M_ROWS, QKV_N, H_DIM);
}
__global__ void __launch_bounds__(256) gemm_proj(float* __restrict__ out) {
    gemm_body(g_attn, g_wproj, out, M_ROWS, H_DIM, H_DIM);
}

// ================= RoPE + head-permute (tf32; Q/K d-permuted) ============
__global__ void __launch_bounds__(256) rope_permute() {
    int idx = blockIdx.x * blockDim.x + threadIdx.x;
    if (idx >= (3 << 22)) return;
    const int pos    = idx & 63;                        // storage position
    const int s      = (idx >> 6) & 2047;
    const int bh     = (idx >> 17) & 31;
    const int region = idx >> 22;                       // 0=q 1=k 2=v
    const int b = bh >> 4, h = bh & 15;
    const int m = b * S_LEN + s;

    const float* src = g_qkv + (size_t)m * QKV_N + region * H_DIM + h * HD;
    float val;
    if (region == 2) {
        val = src[pos];                                 // V: true order
    } else {
        int low = pos & 7;
        int d = (pos & ~7) | ((low >> 1) | ((low & 1) << 2));   // true d
        if (d >= 32) {
            val = src[d];
        } else {
            const float c  = g_cos[s * 32 + d];
            const float sn = g_sin[s * 32 + d];
            const float x0 = src[d];
            const float xr = (d < 16) ? -src[d + 16] : src[d - 16];
            val = fmaf(x0, c, xr * sn);
        }
    }
    float* dst = (region == 0) ? g_q : (region == 1) ? g_k : g_v;
    dst[((size_t)bh * S_LEN + s) * HD + pos] = f2tf32f(val);
}

// ================= Flash attention (tf32 mma, FMA softmax) ===============
// CTA: 128 Q rows x bh. 8 warps; warp owns 16 Q rows.  KV chunks of 64,
// 2-stage cp.async.  Q/K d-permuted -> float2 frag loads in QK^T.
// smem = (128*68 + 2*64*68 + 2*64*72) * 4 = 106496 B.
__global__ void __launch_bounds__(256) flash_attn() {
    extern __shared__ float sm[];
    float* Qs = sm;                       // 128*68
    float* Ks = sm + 8704;                // 2*64*68
    float* Vs = sm + 8704 + 8704;         // 2*64*72

    const int tid = threadIdx.x;
    const int warp = tid >> 5, lane = tid & 31;
    const int g = lane >> 2, q4 = lane & 3;
    const int q0 = blockIdx.x * 128;
    const int bh = blockIdx.y;

    const float* Qg = g_q + ((size_t)bh * S_LEN + q0) * HD;
    const float* Kb = g_k + (size_t)bh * S_LEN * HD;
    const float* Vb = g_v + (size_t)bh * S_LEN * HD;

    {
        int qr = tid >> 1, d0 = (tid & 1) * 32;
        uint32_t dst = (uint32_t)__cvta_generic_to_shared(Qs) + (qr * 68 + d0) * 4;
        const float* src = Qg + qr * 64 + d0;
#pragma unroll
        for (int j = 0; j < 8; ++j) cp16(dst + j * 16, src + j * 4);
    }
    const int kc = tid >> 2, kd = (tid & 3) * 16;
    uint32_t sK = (uint32_t)__cvta_generic_to_shared(Ks) + (kc * 68 + kd) * 4;
    uint32_t sV = (uint32_t)__cvta_generic_to_shared(Vs) + (kc * 72 + kd) * 4;
    auto issueKV = [&](int chunk) {
        int buf = chunk & 1;
        const float* kg = Kb + (size_t)chunk * 64 * 64 + kc * 64 + kd;
        const float* vg = Vb + (size_t)chunk * 64 * 64 + kc * 64 + kd;
        uint32_t dk = sK + buf * (64 * 68 * 4);
        uint32_t dv = sV + buf * (64 * 72 * 4);
#pragma unroll
        for (int j = 0; j < 4; ++j) { cp16(dk + j * 16, kg + j * 4); cp16(dv + j * 16, vg + j * 4); }
        cp_commit();
    };
    issueKV(0);

    const int wq = warp * 16;
    uint32_t qf[8][4];
    float o[8][4] = {};
    float m0 = -1e30f, m1 = -1e30f, l0 = 0.f, l1 = 0.f;
    const float CE = 0.125f * 1.44269504088896f;   // scale * log2(e)

    const int nChunks = S_LEN / 64;
    for (int it = 0; it < nChunks; ++it) {
        if (it + 1 < nChunks) { issueKV(it + 1); cp_wait<1>(); }
        else                  { cp_wait<0>(); }
        __syncthreads();
        if (it == 0) {
#pragma unroll
            for (int kk = 0; kk < 8; ++kk) {
                const float* base = Qs + (wq + g) * 68 + kk * 8 + 2 * q4;
                float2 lo = *(const float2*)base;
                float2 hi = *(const float2*)(base + 8 * 68);
                qf[kk][0] = __float_as_uint(lo.x);
                qf[kk][1] = __float_as_uint(hi.x);
                qf[kk][2] = __float_as_uint(lo.y);
                qf[kk][3] = __float_as_uint(hi.y);
            }
        }
        const float* Kc = Ks + (it & 1) * (64 * 68);
        const float* Vc = Vs + (it & 1) * (64 * 72);

        // ---- scores: S(16x64) = Q K^T ----
        float s[8][4] = {};
#pragma unroll
        for (int kk = 0; kk < 8; ++kk) {
#pragma unroll
            for (int nt = 0; nt < 8; ++nt) {
                float2 bb = *(const float2*)(Kc + (nt * 8 + g) * 68 + kk * 8 + 2 * q4);
                uint32_t bf[2] = { __float_as_uint(bb.x), __float_as_uint(bb.y) };
                mma8(s[nt], qf[kk], bf);
            }
        }

        // ---- online softmax ----
        float mx0 = -1e30f, mx1 = -1e30f;
#pragma unroll
        for (int nt = 0; nt < 8; ++nt) {
            mx0 = fmaxf(mx0, fmaxf(s[nt][0], s[nt][1]));
            mx1 = fmaxf(mx1, fmaxf(s[nt][2], s[nt][3]));
        }
        mx0 = fmaxf(mx0, __shfl_xor_sync(0xffffffffu, mx0, 1));
        mx0 = fmaxf(mx0, __shfl_xor_sync(0xffffffffu, mx0, 2));
        mx1 = fmaxf(mx1, __shfl_xor_sync(0xffffffffu, mx1, 1));
        mx1 = fmaxf(mx1, __shfl_xor_sync(0xffffffffu, mx1, 2));

        float mn0 = fmaxf(m0, mx0), mn1 = fmaxf(m1, mx1);
        float al0 = fexp2(CE * (m0 - mn0)), al1 = fexp2(CE * (m1 - mn1));
        m0 = mn0; m1 = mn1;

        float sum0 = 0.f, sum1 = 0.f;
#pragma unroll
        for (int nt = 0; nt < 8; ++nt) {
            s[nt][0] = fexp2(CE * (s[nt][0] - m0));
            s[nt][1] = fexp2(CE * (s[nt][1] - m0));
            s[nt][2] = fexp2(CE * (s[nt][2] - m1));
            s[nt][3] = fexp2(CE * (s[nt][3] - m1));
            sum0 += s[nt][0] + s[nt][1];
            sum1 += s[nt][2] + s[nt][3];
        }
        sum0 += __shfl_xor_sync(0xffffffffu, sum0, 1);
        sum0 += __shfl_xor_sync(0xffffffffu, sum0, 2);
        sum1 += __shfl_xor_sync(0xffffffffu, sum1, 1);
        sum1 += __shfl_xor_sync(0xffffffffu, sum1, 2);
        l0 = l0 * al0 + sum0;
        l1 = l1 * al1 + sum1;
#pragma unroll
        for (int dt = 0; dt < 8; ++dt) {
            o[dt][0] *= al0; o[dt][1] *= al0; o[dt][2] *= al1; o[dt][3] *= al1;
        }

        // ---- PV: O += P V  (V true order; O comes out true d order) ----
#pragma unroll
        for (int kt = 0; kt < 8; ++kt) {
            uint32_t pa[4];
            cfrag_to_afrag(s[kt], pa);
#pragma unroll
            for (int dt = 0; dt < 8; ++dt) {
                uint32_t bf[2];
                const float* base = Vc + (kt * 8 + q4) * 72 + dt * 8 + g;
                bf[0] = __float_as_uint(base[0]);
                bf[1] = __float_as_uint(base[4 * 72]);
                mma8(o[dt], pa, bf);
            }
        }
        __syncthreads();
    }

    // ---- epilogue: normalize + tf32 + COLUMN-PERMUTED write for proj ----
    // thread holds true cols (2q4, 2q4+1) of each dt 8-block;
    // storage position of true col c: p(c) = ((c&3)<<1) | (c>>2).
    const float inv0 = 1.0f / l0, inv1 = 1.0f / l1;
    const int b = bh >> 4, h = bh & 15;
    const int r0 = q0 + wq + g, r1 = r0 + 8;
    const int p0 = ((q4 & 1) << 2) | (q4 >> 1);        // p(2q4); p(2q4+1)=p0+2
    float* O0 = g_attn + ((size_t)(b * S_LEN) + r0) * H_DIM + h * HD;
    float* O1 = g_attn + ((size_t)(b * S_LEN) + r1) * H_DIM + h * HD;
#pragma unroll
    for (int dt = 0; dt < 8; ++dt) {
        int c = dt * 8 + p0;
        O0[c]     = f2tf32f(o[dt][0] * inv0);
        O0[c + 2] = f2tf32f(o[dt][1] * inv0);
        O1[c]     = f2tf32f(o[dt][2] * inv1);
        O1[c + 2] = f2tf32f(o[dt][3] * inv1);
    }
}

// ================= launch =================
extern "C" void kernel_launch(void* const* d_in, const int* in_sizes, int n_in,
                              void* d_out, int out_size)
{
    const float* x     = (const float*)d_in[0];   // [2,2048,1024]
    const float* Wqkv  = (const float*)d_in[1];   // [3072,1024]
    const float* Wproj = (const float*)d_in[2];   // [1024,1024]
    float* out = (float*)d_out;                   // [2,2048,1024]

    const int GEMM_SMEM  = 2 * 2 * 128 * 36 * 4;                       // 73728
    const int FLASH_SMEM = (128 * 68 + 2 * 64 * 68 + 2 * 64 * 72) * 4; // 106496
    cudaFuncSetAttribute(gemm_qkv,  cudaFuncAttributeMaxDynamicSharedMemorySize, GEMM_SMEM);
    cudaFuncSetAttribute(gemm_proj, cudaFuncAttributeMaxDynamicSharedMemorySize, GEMM_SMEM);
    cudaFuncSetAttribute(flash_attn, cudaFuncAttributeMaxDynamicSharedMemorySize, FLASH_SMEM);

    init_rope_tables<<<(S_LEN * 32 + 255) / 256, 256>>>();
    cvt_x    <<<(M_ROWS * H_DIM / 8 + 255) / 256, 256>>>(x);
    cvt_wqkv <<<(QKV_N  * H_DIM / 8 + 255) / 256, 256>>>(Wqkv);
    cvt_wproj<<<(H_DIM  * H_DIM / 8 + 255) / 256, 256>>>(Wproj);

    gemm_qkv<<<dim3(QKV_N / 128, M_ROWS / 128), 256, GEMM_SMEM>>>();
    rope_permute<<<(3 << 22) / 256, 256>>>();
    flash_attn<<<dim3(S_LEN / 128, BH_TOT), 256, FLASH_SMEM>>>();
    gemm_proj<<<dim3(H_DIM / 128, M_ROWS / 128), 256, GEMM_SMEM>>>(out);
}

// round 13
// speedup vs baseline: 1.3930x; 1.0032x over previous
#include <cuda_runtime.h>
#include <math.h>
#include <stdint.h>

// Problem constants
#define S_LEN   2048
#define NH      16
#define HD      64
#define BH_TOT  32          // B * NH
#define M_ROWS  4096        // B * S
#define H_DIM   1024
#define QKV_N   3072

// Contraction-dim permutation (groups of 8): storage [k0,k4,k1,k5,k2,k6,k3,k7].
// Applied to x/Wqkv/Wproj K-dims, Q/K head-dims, g_attn columns.
// mma fragment k-pair (q4, q4+4) becomes adjacent -> float2 loads.

// -------- scratch (device globals: no allocation allowed) --------
__device__ float g_qkv[(size_t)M_ROWS * QKV_N];          // fp32, TRUE col order
__device__ float g_q[(size_t)BH_TOT * S_LEN * HD];       // tf32, d-permuted
__device__ float g_k[(size_t)BH_TOT * S_LEN * HD];       // tf32, d-permuted
__device__ float g_v[(size_t)BH_TOT * S_LEN * HD];       // tf32, TRUE order
__device__ float g_attn[(size_t)M_ROWS * H_DIM];         // tf32, col-permuted
__device__ float g_xa[(size_t)M_ROWS * H_DIM];           // tf32, k-permuted
__device__ float g_wqkv[(size_t)QKV_N * H_DIM];          // tf32, k-permuted
__device__ float g_wproj[(size_t)H_DIM * H_DIM];         // tf32, k-permuted
__device__ float g_cos[S_LEN * 32];
__device__ float g_sin[S_LEN * 32];

// ================= small helpers =================
__device__ __forceinline__ uint32_t f2tf32(float x) {
    uint32_t r; asm("cvt.rna.tf32.f32 %0, %1;" : "=r"(r) : "f"(x)); return r;
}
__device__ __forceinline__ float f2tf32f(float x) { return __uint_as_float(f2tf32(x)); }

__device__ __forceinline__ void mma8(float d[4], const uint32_t a[4], const uint32_t b[2]) {
    asm volatile("mma.sync.aligned.m16n8k8.row.col.f32.tf32.tf32.f32 "
                 "{%0,%1,%2,%3}, {%4,%5,%6,%7}, {%8,%9}, {%0,%1,%2,%3};\n"
                 : "+f"(d[0]), "+f"(d[1]), "+f"(d[2]), "+f"(d[3])
                 : "r"(a[0]), "r"(a[1]), "r"(a[2]), "r"(a[3]),
                   "r"(b[0]), "r"(b[1]));
}

__device__ __forceinline__ void cp16(uint32_t s, const void* g) {
    asm volatile("cp.async.cg.shared.global [%0], [%1], 16;" :: "r"(s), "l"(g));
}
__device__ __forceinline__ void cp_commit() { asm volatile("cp.async.commit_group;"); }
template<int N> __device__ __forceinline__ void cp_wait() {
    asm volatile("cp.async.wait_group %0;" :: "n"(N));
}

// pure-FMA exp2 (degree-6; rel err ~1e-7). No MUFU.
__device__ __forceinline__ float fexp2(float x) {
    x = fmaxf(x, -100.f);
    float i = rintf(x);
    float f = x - i;
    float p = fmaf(f, 1.54035304e-4f, 1.33335581e-3f);
    p = fmaf(p, f, 9.61812911e-3f);
    p = fmaf(p, f, 5.55041087e-2f);
    p = fmaf(p, f, 2.40226507e-1f);
    p = fmaf(p, f, 6.93147181e-1f);
    p = fmaf(p, f, 1.0f);
    return __int_as_float(__float_as_int(p) + (((int)i) << 23));
}

// C-fragment (m16n8 f32) -> A-fragment (m16k8 tf32) of the SAME 16x8 tile.
__device__ __forceinline__ void cfrag_to_afrag(const float c[4], uint32_t a[4]) {
    int t = threadIdx.x & 31;
    int src0 = (t & 28) | ((t & 3) >> 1);
    int src2 = src0 + 2;
    float x00 = __shfl_sync(0xffffffffu, c[0], src0);
    float x01 = __shfl_sync(0xffffffffu, c[1], src0);
    float x10 = __shfl_sync(0xffffffffu, c[2], src0);
    float x11 = __shfl_sync(0xffffffffu, c[3], src0);
    float y00 = __shfl_sync(0xffffffffu, c[0], src2);
    float y01 = __shfl_sync(0xffffffffu, c[1], src2);
    float y10 = __shfl_sync(0xffffffffu, c[2], src2);
    float y11 = __shfl_sync(0xffffffffu, c[3], src2);
    bool odd = t & 1;
    a[0] = f2tf32(odd ? x01 : x00);
    a[1] = f2tf32(odd ? x11 : x10);
    a[2] = f2tf32(odd ? y01 : y00);
    a[3] = f2tf32(odd ? y11 : y10);
}

// ================= fused prep: rope tables + 3x (tf32 round + k-permute) ==
// Block ranges:  [0,2048) x -> g_xa | [2048,3584) Wqkv | [3584,4096) Wproj
//                [4096,4352) rope tables.
__device__ __forceinline__ void cvt_perm8_body(
    const float* __restrict__ in, float* __restrict__ out, int blk)
{
    int gi = blk * 256 + threadIdx.x;
    const float4* p = (const float4*)(in + (size_t)gi * 8);
    float4 a = p[0], b = p[1];          // a = k0..3, b = k4..7
    float4 o0 = make_float4(f2tf32f(a.x), f2tf32f(b.x), f2tf32f(a.y), f2tf32f(b.y));
    float4 o1 = make_float4(f2tf32f(a.z), f2tf32f(b.z), f2tf32f(a.w), f2tf32f(b.w));
    float4* q = (float4*)(out + (size_t)gi * 8);
    q[0] = o0; q[1] = o1;
}

__global__ void __launch_bounds__(256) prep(
    const float* __restrict__ x, const float* __restrict__ Wqkv,
    const float* __restrict__ Wproj)
{
    int b = blockIdx.x;
    if (b < 2048) {                       // x: n8 = 4096*1024/8 = 524288
        cvt_perm8_body(x, g_xa, b);
    } else if (b < 3584) {                // Wqkv: n8 = 3072*1024/8 = 393216
        cvt_perm8_body(Wqkv, g_wqkv, b - 2048);
    } else if (b < 4096) {                // Wproj: n8 = 1024*1024/8 = 131072
        cvt_perm8_body(Wproj, g_wproj, b - 3584);
    } else {                              // rope tables: 65536 entries
        int idx = (b - 4096) * 256 + threadIdx.x;
        int s = idx >> 5, j = idx & 31;
        double invf = exp(-log(10000.0) * (double)j / 32.0);
        double ang  = (double)s * invf;
        g_cos[idx] = (float)cos(ang);
        g_sin[idx] = (float)sin(ang);
    }
}

// ================= tf32 GEMM: C[M][N] = A[M][K] * B[N][K]^T ===============
// A,B tf32-rounded AND k-permuted; C written in TRUE n-order.
// CTA 128x128, k-chunk 32, 8 warps (4x2), warp 32x64, 2-stage cp.async.
// smem 73728 B; 2 CTAs/SM (147KB smem, ~110 regs) for latency hiding.
__device__ __forceinline__ void gemm_body(
    const float* __restrict__ A, const float* __restrict__ B,
    float* __restrict__ C, int M, int N, int K)
{
    extern __shared__ float sm[];
    float* As = sm;
    float* Bs = sm + 2 * 128 * 36;

    const int tid = threadIdx.x;
    const int bm = blockIdx.y * 128, bn = blockIdx.x * 128;

    const int lr = tid >> 1;
    const int k0 = (tid & 1) << 4;
    const float* Ag = A + (size_t)(bm + lr) * K + k0;
    const float* Bg = B + (size_t)(bn + lr) * K + k0;
    uint32_t sA = (uint32_t)__cvta_generic_to_shared(As) + (lr * 36 + k0) * 4;
    uint32_t sB = (uint32_t)__cvta_generic_to_shared(Bs) + (lr * 36 + k0) * 4;
    const uint32_t bufB = 128 * 36 * 4;

    auto issue = [&](int chunk) {
        int buf = chunk & 1;
        const float* a = Ag + chunk * 32;
        const float* b = Bg + chunk * 32;
        uint32_t da = sA + buf * bufB;
        uint32_t db = sB + buf * bufB;
#pragma unroll
        for (int j = 0; j < 4; ++j) { cp16(da + j * 16, a + j * 4); cp16(db + j * 16, b + j * 4); }
        cp_commit();
    };

    issue(0);

    const int warp = tid >> 5, lane = tid & 31;
    const int g = lane >> 2, q4 = lane & 3;
    const int wm = (warp >> 1) * 32;
    const int wn = (warp & 1) * 64;

    float acc[2][8][4] = {};
    const int nChunks = K >> 5;
    for (int it = 0; it < nChunks; ++it) {
        if (it + 1 < nChunks) { issue(it + 1); cp_wait<1>(); }
        else                  { cp_wait<0>(); }
        __syncthreads();
        const float* Ab = As + (it & 1) * (128 * 36);
        const float* Bb = Bs + (it & 1) * (128 * 36);
#pragma unroll
        for (int kk = 0; kk < 4; ++kk) {
            uint32_t af[2][4];
#pragma unroll
            for (int mi = 0; mi < 2; ++mi) {
                const float* base = Ab + (wm + mi * 16 + g) * 36 + kk * 8 + 2 * q4;
                float2 lo = *(const float2*)base;            // true k = q4
                float2 hi = *(const float2*)(base + 8 * 36); // rows +8
                af[mi][0] = __float_as_uint(lo.x);
                af[mi][1] = __float_as_uint(hi.x);
                af[mi][2] = __float_as_uint(lo.y);           // true k = q4+4
                af[mi][3] = __float_as_uint(hi.y);
            }
#pragma unroll
            for (int j = 0; j < 8; ++j) {
                float2 bb = *(const float2*)(Bb + (wn + j * 8 + g) * 36 + kk * 8 + 2 * q4);
                uint32_t bf[2] = { __float_as_uint(bb.x), __float_as_uint(bb.y) };
                mma8(acc[0][j], af[0], bf);
                mma8(acc[1][j], af[1], bf);
            }
        }
        __syncthreads();
    }

#pragma unroll
    for (int mi = 0; mi < 2; ++mi)
#pragma unroll
        for (int r = 0; r < 2; ++r) {
            int row = bm + wm + mi * 16 + g + r * 8;
            float* Cp = C + (size_t)row * N + bn + wn;
#pragma unroll
            for (int j = 0; j < 8; ++j) {
                float2 v = make_float2(acc[mi][j][r * 2], acc[mi][j][r * 2 + 1]);
                *(float2*)(Cp + j * 8 + q4 * 2) = v;
            }
        }
}

__global__ void __launch_bounds__(256, 2) gemm_qkv() {
    gemm_body(g_xa, g_wqkv, g_qkv, M_ROWS, QKV_N, H_DIM);
}
__global__ void __launch_bounds__(256, 2) gemm_proj(float* __restrict__ out) {
    gemm_body(g_attn, g_wproj, out, M_ROWS, H_DIM, H_DIM);
}

// ================= RoPE + head-permute (tf32; Q/K d-permuted) ============
__global__ void __launch_bounds__(256) rope_permute() {
    int idx = blockIdx.x * blockDim.x + threadIdx.x;
    if (idx >= (3 << 22)) return;
    const int pos    = idx & 63;                        // storage position
    const int s      = (idx >> 6) & 2047;
    const int bh     = (idx >> 17) & 31;
    const int region = idx >> 22;                       // 0=q 1=k 2=v
    const int b = bh >> 4, h = bh & 15;
    const int m = b * S_LEN + s;

    const float* src = g_qkv + (size_t)m * QKV_N + region * H_DIM + h * HD;
    float val;
    if (region == 2) {
        val = src[pos];                                 // V: true order
    } else {
        int low = pos & 7;
        int d = (pos & ~7) | ((low >> 1) | ((low & 1) << 2));   // true d
        if (d >= 32) {
            val = src[d];
        } else {
            const float c  = g_cos[s * 32 + d];
            const float sn = g_sin[s * 32 + d];
            const float x0 = src[d];
            const float xr = (d < 16) ? -src[d + 16] : src[d - 16];
            val = fmaf(x0, c, xr * sn);
        }
    }
    float* dst = (region == 0) ? g_q : (region == 1) ? g_k : g_v;
    dst[((size_t)bh * S_LEN + s) * HD + pos] = f2tf32f(val);
}

// ================= Flash attention (tf32 mma, FMA softmax) ===============
// CTA: 128 Q rows x bh. 8 warps; warp owns 16 Q rows.  KV chunks of 64,
// 2-stage cp.async.  Q/K d-permuted -> float2 frag loads in QK^T.
// smem = (128*68 + 2*64*68 + 2*64*72) * 4 = 106496 B.
__global__ void __launch_bounds__(256) flash_attn() {
    extern __shared__ float sm[];
    float* Qs = sm;                       // 128*68
    float* Ks = sm + 8704;                // 2*64*68
    float* Vs = sm + 8704 + 8704;         // 2*64*72

    const int tid = threadIdx.x;
    const int warp = tid >> 5, lane = tid & 31;
    const int g = lane >> 2, q4 = lane & 3;
    const int q0 = blockIdx.x * 128;
    const int bh = blockIdx.y;

    const float* Qg = g_q + ((size_t)bh * S_LEN + q0) * HD;
    const float* Kb = g_k + (size_t)bh * S_LEN * HD;
    const float* Vb = g_v + (size_t)bh * S_LEN * HD;

    {
        int qr = tid >> 1, d0 = (tid & 1) * 32;
        uint32_t dst = (uint32_t)__cvta_generic_to_shared(Qs) + (qr * 68 + d0) * 4;
        const float* src = Qg + qr * 64 + d0;
#pragma unroll
        for (int j = 0; j < 8; ++j) cp16(dst + j * 16, src + j * 4);
    }
    const int kc = tid >> 2, kd = (tid & 3) * 16;
    uint32_t sK = (uint32_t)__cvta_generic_to_shared(Ks) + (kc * 68 + kd) * 4;
    uint32_t sV = (uint32_t)__cvta_generic_to_shared(Vs) + (kc * 72 + kd) * 4;
    auto issueKV = [&](int chunk) {
        int buf = chunk & 1;
        const float* kg = Kb + (size_t)chunk * 64 * 64 + kc * 64 + kd;
        const float* vg = Vb + (size_t)chunk * 64 * 64 + kc * 64 + kd;
        uint32_t dk = sK + buf * (64 * 68 * 4);
        uint32_t dv = sV + buf * (64 * 72 * 4);
#pragma unroll
        for (int j = 0; j < 4; ++j) { cp16(dk + j * 16, kg + j * 4); cp16(dv + j * 16, vg + j * 4); }
        cp_commit();
    };
    issueKV(0);

    const int wq = warp * 16;
    uint32_t qf[8][4];
    float o[8][4] = {};
    float m0 = -1e30f, m1 = -1e30f, l0 = 0.f, l1 = 0.f;
    const float CE = 0.125f * 1.44269504088896f;   // scale * log2(e)

    const int nChunks = S_LEN / 64;
    for (int it = 0; it < nChunks; ++it) {
        if (it + 1 < nChunks) { issueKV(it + 1); cp_wait<1>(); }
        else                  { cp_wait<0>(); }
        __syncthreads();
        if (it == 0) {
#pragma unroll
            for (int kk = 0; kk < 8; ++kk) {
                const float* base = Qs + (wq + g) * 68 + kk * 8 + 2 * q4;
                float2 lo = *(const float2*)base;
                float2 hi = *(const float2*)(base + 8 * 68);
                qf[kk][0] = __float_as_uint(lo.x);
                qf[kk][1] = __float_as_uint(hi.x);
                qf[kk][2] = __float_as_uint(lo.y);
                qf[kk][3] = __float_as_uint(hi.y);
            }
        }
        const float* Kc = Ks + (it & 1) * (64 * 68);
        const float* Vc = Vs + (it & 1) * (64 * 72);

        // ---- scores: S(16x64) = Q K^T ----
        float s[8][4] = {};
#pragma unroll
        for (int kk = 0; kk < 8; ++kk) {
#pragma unroll
            for (int nt = 0; nt < 8; ++nt) {
                float2 bb = *(const float2*)(Kc + (nt * 8 + g) * 68 + kk * 8 + 2 * q4);
                uint32_t bf[2] = { __float_as_uint(bb.x), __float_as_uint(bb.y) };
                mma8(s[nt], qf[kk], bf);
            }
        }

        // ---- online softmax ----
        float mx0 = -1e30f, mx1 = -1e30f;
#pragma unroll
        for (int nt = 0; nt < 8; ++nt) {
            mx0 = fmaxf(mx0, fmaxf(s[nt][0], s[nt][1]));
            mx1 = fmaxf(mx1, fmaxf(s[nt][2], s[nt][3]));
        }
        mx0 = fmaxf(mx0, __shfl_xor_sync(0xffffffffu, mx0, 1));
        mx0 = fmaxf(mx0, __shfl_xor_sync(0xffffffffu, mx0, 2));
        mx1 = fmaxf(mx1, __shfl_xor_sync(0xffffffffu, mx1, 1));
        mx1 = fmaxf(mx1, __shfl_xor_sync(0xffffffffu, mx1, 2));

        float mn0 = fmaxf(m0, mx0), mn1 = fmaxf(m1, mx1);
        float al0 = fexp2(CE * (m0 - mn0)), al1 = fexp2(CE * (m1 - mn1));
        m0 = mn0; m1 = mn1;

        float sum0 = 0.f, sum1 = 0.f;
#pragma unroll
        for (int nt = 0; nt < 8; ++nt) {
            s[nt][0] = fexp2(CE * (s[nt][0] - m0));
            s[nt][1] = fexp2(CE * (s[nt][1] - m0));
            s[nt][2] = fexp2(CE * (s[nt][2] - m1));
            s[nt][3] = fexp2(CE * (s[nt][3] - m1));
            sum0 += s[nt][0] + s[nt][1];
            sum1 += s[nt][2] + s[nt][3];
        }
        sum0 += __shfl_xor_sync(0xffffffffu, sum0, 1);
        sum0 += __shfl_xor_sync(0xffffffffu, sum0, 2);
        sum1 += __shfl_xor_sync(0xffffffffu, sum1, 1);
        sum1 += __shfl_xor_sync(0xffffffffu, sum1, 2);
        l0 = l0 * al0 + sum0;
        l1 = l1 * al1 + sum1;
#pragma unroll
        for (int dt = 0; dt < 8; ++dt) {
            o[dt][0] *= al0; o[dt][1] *= al0; o[dt][2] *= al1; o[dt][3] *= al1;
        }

        // ---- PV: O += P V  (V true order; O comes out true d order) ----
#pragma unroll
        for (int kt = 0; kt < 8; ++kt) {
            uint32_t pa[4];
            cfrag_to_afrag(s[kt], pa);
#pragma unroll
            for (int dt = 0; dt < 8; ++dt) {
                uint32_t bf[2];
                const float* base = Vc + (kt * 8 + q4) * 72 + dt * 8 + g;
                bf[0] = __float_as_uint(base[0]);
                bf[1] = __float_as_uint(base[4 * 72]);
                mma8(o[dt], pa, bf);
            }
        }
        __syncthreads();
    }

    // ---- epilogue: normalize + tf32 + COLUMN-PERMUTED write for proj ----
    const float inv0 = 1.0f / l0, inv1 = 1.0f / l1;
    const int b = bh >> 4, h = bh & 15;
    const int r0 = q0 + wq + g, r1 = r0 + 8;
    const int p0 = ((q4 & 1) << 2) | (q4 >> 1);        // p(2q4); p(2q4+1)=p0+2
    float* O0 = g_attn + ((size_t)(b * S_LEN) + r0) * H_DIM + h * HD;
    float* O1 = g_attn + ((size_t)(b * S_LEN) + r1) * H_DIM + h * HD;
#pragma unroll
    for (int dt = 0; dt < 8; ++dt) {
        int c = dt * 8 + p0;
        O0[c]     = f2tf32f(o[dt][0] * inv0);
        O0[c + 2] = f2tf32f(o[dt][1] * inv0);
        O1[c]     = f2tf32f(o[dt][2] * inv1);
        O1[c + 2] = f2tf32f(o[dt][3] * inv1);
    }
}

// ================= launch =================
extern "C" void kernel_launch(void* const* d_in, const int* in_sizes, int n_in,
                              void* d_out, int out_size)
{
    const float* x     = (const float*)d_in[0];   // [2,2048,1024]
    const float* Wqkv  = (const float*)d_in[1];   // [3072,1024]
    const float* Wproj = (const float*)d_in[2];   // [1024,1024]
    float* out = (float*)d_out;                   // [2,2048,1024]

    const int GEMM_SMEM  = 2 * 2 * 128 * 36 * 4;                       // 73728
    const int FLASH_SMEM = (128 * 68 + 2 * 64 * 68 + 2 * 64 * 72) * 4; // 106496
    cudaFuncSetAttribute(gemm_qkv,  cudaFuncAttributeMaxDynamicSharedMemorySize, GEMM_SMEM);
    cudaFuncSetAttribute(gemm_proj, cudaFuncAttributeMaxDynamicSharedMemorySize, GEMM_SMEM);
    cudaFuncSetAttribute(flash_attn, cudaFuncAttributeMaxDynamicSharedMemorySize, FLASH_SMEM);

    // 5 launches; flash_attn is launch #4 (the one ncu captures).
    prep<<<4352, 256>>>(x, Wqkv, Wproj);
    gemm_qkv<<<dim3(QKV_N / 128, M_ROWS / 128), 256, GEMM_SMEM>>>();
    rope_permute<<<(3 << 22) / 256, 256>>>();
    flash_attn<<<dim3(S_LEN / 128, BH_TOT), 256, FLASH_SMEM>>>();
    gemm_proj<<<dim3(H_DIM / 128, M_ROWS / 128), 256, GEMM_SMEM>>>(out);
}

// round 14
// speedup vs baseline: 1.5981x; 1.1473x over previous
#include <cuda_runtime.h>
#include <math.h>
#include <stdint.h>

// Problem constants
#define S_LEN   2048
#define NH      16
#define HD      64
#define BH_TOT  32          // B * NH
#define M_ROWS  4096        // B * S
#define H_DIM   1024
#define QKV_N   3072

// Contraction-dim permutation (groups of 8): storage [k0,k4,k1,k5,k2,k6,k3,k7].
// Applied to x/Wqkv/Wproj K-dims, Q/K head-dims, g_attn columns.
// mma fragment k-pair (q4, q4+4) becomes adjacent -> float2 loads.

// -------- scratch (device globals: no allocation allowed) --------
__device__ float g_qkv[(size_t)M_ROWS * QKV_N];          // fp32, TRUE col order
__device__ float g_q[(size_t)BH_TOT * S_LEN * HD];       // tf32, d-permuted
__device__ float g_k[(size_t)BH_TOT * S_LEN * HD];       // tf32, d-permuted
__device__ float g_v[(size_t)BH_TOT * S_LEN * HD];       // tf32, TRUE order
__device__ float g_attn[(size_t)M_ROWS * H_DIM];         // tf32, col-permuted
__device__ float g_xa[(size_t)M_ROWS * H_DIM];           // tf32, k-permuted
__device__ float g_wqkv[(size_t)QKV_N * H_DIM];          // tf32, k-permuted
__device__ float g_wproj[(size_t)H_DIM * H_DIM];         // tf32, k-permuted
__device__ float g_cos[S_LEN * 32];
__device__ float g_sin[S_LEN * 32];

// ================= small helpers =================
__device__ __forceinline__ uint32_t f2tf32(float x) {
    uint32_t r; asm("cvt.rna.tf32.f32 %0, %1;" : "=r"(r) : "f"(x)); return r;
}
__device__ __forceinline__ float f2tf32f(float x) { return __uint_as_float(f2tf32(x)); }

__device__ __forceinline__ void mma8(float d[4], const uint32_t a[4], const uint32_t b[2]) {
    asm volatile("mma.sync.aligned.m16n8k8.row.col.f32.tf32.tf32.f32 "
                 "{%0,%1,%2,%3}, {%4,%5,%6,%7}, {%8,%9}, {%0,%1,%2,%3};\n"
                 : "+f"(d[0]), "+f"(d[1]), "+f"(d[2]), "+f"(d[3])
                 : "r"(a[0]), "r"(a[1]), "r"(a[2]), "r"(a[3]),
                   "r"(b[0]), "r"(b[1]));
}

__device__ __forceinline__ void cp16(uint32_t s, const void* g) {
    asm volatile("cp.async.cg.shared.global [%0], [%1], 16;" :: "r"(s), "l"(g));
}
__device__ __forceinline__ void cp_commit() { asm volatile("cp.async.commit_group;"); }
template<int N> __device__ __forceinline__ void cp_wait() {
    asm volatile("cp.async.wait_group %0;" :: "n"(N));
}

// pure-FMA exp2 (degree-6; rel err ~1e-7). No MUFU.
__device__ __forceinline__ float fexp2(float x) {
    x = fmaxf(x, -100.f);
    float i = rintf(x);
    float f = x - i;
    float p = fmaf(f, 1.54035304e-4f, 1.33335581e-3f);
    p = fmaf(p, f, 9.61812911e-3f);
    p = fmaf(p, f, 5.55041087e-2f);
    p = fmaf(p, f, 2.40226507e-1f);
    p = fmaf(p, f, 6.93147181e-1f);
    p = fmaf(p, f, 1.0f);
    return __int_as_float(__float_as_int(p) + (((int)i) << 23));
}

// C-fragment (m16n8 f32) -> A-fragment (m16k8 tf32) of the SAME 16x8 tile.
__device__ __forceinline__ void cfrag_to_afrag(const float c[4], uint32_t a[4]) {
    int t = threadIdx.x & 31;
    int src0 = (t & 28) | ((t & 3) >> 1);
    int src2 = src0 + 2;
    float x00 = __shfl_sync(0xffffffffu, c[0], src0);
    float x01 = __shfl_sync(0xffffffffu, c[1], src0);
    float x10 = __shfl_sync(0xffffffffu, c[2], src0);
    float x11 = __shfl_sync(0xffffffffu, c[3], src0);
    float y00 = __shfl_sync(0xffffffffu, c[0], src2);
    float y01 = __shfl_sync(0xffffffffu, c[1], src2);
    float y10 = __shfl_sync(0xffffffffu, c[2], src2);
    float y11 = __shfl_sync(0xffffffffu, c[3], src2);
    bool odd = t & 1;
    a[0] = f2tf32(odd ? x01 : x00);
    a[1] = f2tf32(odd ? x11 : x10);
    a[2] = f2tf32(odd ? y01 : y00);
    a[3] = f2tf32(odd ? y11 : y10);
}

// ================= fused prep: rope tables + 3x (tf32 round + k-permute) ==
__device__ __forceinline__ void cvt_perm8_body(
    const float* __restrict__ in, float* __restrict__ out, int blk)
{
    int gi = blk * 256 + threadIdx.x;
    const float4* p = (const float4*)(in + (size_t)gi * 8);
    float4 a = p[0], b = p[1];          // a = k0..3, b = k4..7
    float4 o0 = make_float4(f2tf32f(a.x), f2tf32f(b.x), f2tf32f(a.y), f2tf32f(b.y));
    float4 o1 = make_float4(f2tf32f(a.z), f2tf32f(b.z), f2tf32f(a.w), f2tf32f(b.w));
    float4* q = (float4*)(out + (size_t)gi * 8);
    q[0] = o0; q[1] = o1;
}

__global__ void __launch_bounds__(256) prep(
    const float* __restrict__ x, const float* __restrict__ Wqkv,
    const float* __restrict__ Wproj)
{
    int b = blockIdx.x;
    if (b < 2048) {                       // x
        cvt_perm8_body(x, g_xa, b);
    } else if (b < 3584) {                // Wqkv
        cvt_perm8_body(Wqkv, g_wqkv, b - 2048);
    } else if (b < 4096) {                // Wproj
        cvt_perm8_body(Wproj, g_wproj, b - 3584);
    } else {                              // rope tables
        int idx = (b - 4096) * 256 + threadIdx.x;
        int s = idx >> 5, j = idx & 31;
        double invf = exp(-log(10000.0) * (double)j / 32.0);
        double ang  = (double)s * invf;
        g_cos[idx] = (float)cos(ang);
        g_sin[idx] = (float)sin(ang);
    }
}

// ================= tf32 GEMM: C[M][N] = A[M][K] * B[N][K]^T ===============
__device__ __forceinline__ void gemm_body(
    const float* __restrict__ A, const float* __restrict__ B,
    float* __restrict__ C, int M, int N, int K)
{
    extern __shared__ float sm[];
    float* As = sm;
    float* Bs = sm + 2 * 128 * 36;

    const int tid = threadIdx.x;
    const int bm = blockIdx.y * 128, bn = blockIdx.x * 128;

    const int lr = tid >> 1;
    const int k0 = (tid & 1) << 4;
    const float* Ag = A + (size_t)(bm + lr) * K + k0;
    const float* Bg = B + (size_t)(bn + lr) * K + k0;
    uint32_t sA = (uint32_t)__cvta_generic_to_shared(As) + (lr * 36 + k0) * 4;
    uint32_t sB = (uint32_t)__cvta_generic_to_shared(Bs) + (lr * 36 + k0) * 4;
    const uint32_t bufB = 128 * 36 * 4;

    auto issue = [&](int chunk) {
        int buf = chunk & 1;
        const float* a = Ag + chunk * 32;
        const float* b = Bg + chunk * 32;
        uint32_t da = sA + buf * bufB;
        uint32_t db = sB + buf * bufB;
#pragma unroll
        for (int j = 0; j < 4; ++j) { cp16(da + j * 16, a + j * 4); cp16(db + j * 16, b + j * 4); }
        cp_commit();
    };

    issue(0);

    const int warp = tid >> 5, lane = tid & 31;
    const int g = lane >> 2, q4 = lane & 3;
    const int wm = (warp >> 1) * 32;
    const int wn = (warp & 1) * 64;

    float acc[2][8][4] = {};
    const int nChunks = K >> 5;
    for (int it = 0; it < nChunks; ++it) {
        if (it + 1 < nChunks) { issue(it + 1); cp_wait<1>(); }
        else                  { cp_wait<0>(); }
        __syncthreads();
        const float* Ab = As + (it & 1) * (128 * 36);
        const float* Bb = Bs + (it & 1) * (128 * 36);
#pragma unroll
        for (int kk = 0; kk < 4; ++kk) {
            uint32_t af[2][4];
#pragma unroll
            for (int mi = 0; mi < 2; ++mi) {
                const float* base = Ab + (wm + mi * 16 + g) * 36 + kk * 8 + 2 * q4;
                float2 lo = *(const float2*)base;
                float2 hi = *(const float2*)(base + 8 * 36);
                af[mi][0] = __float_as_uint(lo.x);
                af[mi][1] = __float_as_uint(hi.x);
                af[mi][2] = __float_as_uint(lo.y);
                af[mi][3] = __float_as_uint(hi.y);
            }
#pragma unroll
            for (int j = 0; j < 8; ++j) {
                float2 bb = *(const float2*)(Bb + (wn + j * 8 + g) * 36 + kk * 8 + 2 * q4);
                uint32_t bf[2] = { __float_as_uint(bb.x), __float_as_uint(bb.y) };
                mma8(acc[0][j], af[0], bf);
                mma8(acc[1][j], af[1], bf);
            }
        }
        __syncthreads();
    }

#pragma unroll
    for (int mi = 0; mi < 2; ++mi)
#pragma unroll
        for (int r = 0; r < 2; ++r) {
            int row = bm + wm + mi * 16 + g + r * 8;
            float* Cp = C + (size_t)row * N + bn + wn;
#pragma unroll
            for (int j = 0; j < 8; ++j) {
                float2 v = make_float2(acc[mi][j][r * 2], acc[mi][j][r * 2 + 1]);
                *(float2*)(Cp + j * 8 + q4 * 2) = v;
            }
        }
}

__global__ void __launch_bounds__(256, 2) gemm_qkv() {
    gemm_body(g_xa, g_wqkv, g_qkv, M_ROWS, QKV_N, H_DIM);
}
__global__ void __launch_bounds__(256, 2) gemm_proj(float* __restrict__ out) {
    gemm_body(g_attn, g_wproj, out, M_ROWS, H_DIM, H_DIM);
}

// ================= RoPE + head-permute (tf32; Q/K d-permuted) ============
__global__ void __launch_bounds__(256) rope_permute() {
    int idx = blockIdx.x * blockDim.x + threadIdx.x;
    if (idx >= (3 << 22)) return;
    const int pos    = idx & 63;
    const int s      = (idx >> 6) & 2047;
    const int bh     = (idx >> 17) & 31;
    const int region = idx >> 22;                       // 0=q 1=k 2=v
    const int b = bh >> 4, h = bh & 15;
    const int m = b * S_LEN + s;

    const float* src = g_qkv + (size_t)m * QKV_N + region * H_DIM + h * HD;
    float val;
    if (region == 2) {
        val = src[pos];
    } else {
        int low = pos & 7;
        int d = (pos & ~7) | ((low >> 1) | ((low & 1) << 2));   // true d
        if (d >= 32) {
            val = src[d];
        } else {
            const float c  = g_cos[s * 32 + d];
            const float sn = g_sin[s * 32 + d];
            const float x0 = src[d];
            const float xr = (d < 16) ? -src[d + 16] : src[d - 16];
            val = fmaf(x0, c, xr * sn);
        }
    }
    float* dst = (region == 0) ? g_q : (region == 1) ? g_k : g_v;
    dst[((size_t)bh * S_LEN + s) * HD + pos] = f2tf32f(val);
}

// ================= Flash attention (tf32 mma, FMA softmax) ===============
// CTA: 128 Q rows x bh. 8 warps; warp owns 16 Q rows.  KV chunks of 32,
// 2-stage cp.async.  2 CTAs/SM (smem 70656B x2 = 138KB, regs <=128).
// smem = (128*68 + 2*32*68 + 2*32*72) * 4 = 70656 B.
#define FCHUNK 32
__global__ void __launch_bounds__(256, 2) flash_attn() {
    extern __shared__ float sm[];
    float* Qs = sm;                        // 128*68
    float* Ks = sm + 8704;                 // 2*32*68
    float* Vs = sm + 8704 + 2 * 32 * 68;   // 2*32*72

    const int tid = threadIdx.x;
    const int warp = tid >> 5, lane = tid & 31;
    const int g = lane >> 2, q4 = lane & 3;
    const int q0 = blockIdx.x * 128;
    const int bh = blockIdx.y;

    const float* Qg = g_q + ((size_t)bh * S_LEN + q0) * HD;
    const float* Kb = g_k + (size_t)bh * S_LEN * HD;
    const float* Vb = g_v + (size_t)bh * S_LEN * HD;

    {   // Q load (cp.async group 0)
        int qr = tid >> 1, d0 = (tid & 1) * 32;
        uint32_t dst = (uint32_t)__cvta_generic_to_shared(Qs) + (qr * 68 + d0) * 4;
        const float* src = Qg + qr * 64 + d0;
#pragma unroll
        for (int j = 0; j < 8; ++j) cp16(dst + j * 16, src + j * 4);
    }
    const int kc = tid >> 3;               // 0..31 row
    const int kd = (tid & 7) * 8;          // col block of 8
    uint32_t sK = (uint32_t)__cvta_generic_to_shared(Ks) + (kc * 68 + kd) * 4;
    uint32_t sV = (uint32_t)__cvta_generic_to_shared(Vs) + (kc * 72 + kd) * 4;
    auto issueKV = [&](int chunk) {
        int buf = chunk & 1;
        const float* kg = Kb + (size_t)chunk * FCHUNK * 64 + kc * 64 + kd;
        const float* vg = Vb + (size_t)chunk * FCHUNK * 64 + kc * 64 + kd;
        uint32_t dk = sK + buf * (32 * 68 * 4);
        uint32_t dv = sV + buf * (32 * 72 * 4);
#pragma unroll
        for (int j = 0; j < 2; ++j) { cp16(dk + j * 16, kg + j * 4); cp16(dv + j * 16, vg + j * 4); }
        cp_commit();
    };
    issueKV(0);   // group 0 = Q + K0 + V0

    const int wq = warp * 16;
    uint32_t qf[8][4];
    float o[8][4] = {};
    float m0 = -1e30f, m1 = -1e30f, l0 = 0.f, l1 = 0.f;
    const float CE = 0.125f * 1.44269504088896f;   // scale * log2(e)

    const int nChunks = S_LEN / FCHUNK;
    for (int it = 0; it < nChunks; ++it) {
        if (it + 1 < nChunks) { issueKV(it + 1); cp_wait<1>(); }
        else                  { cp_wait<0>(); }
        __syncthreads();
        if (it == 0) {
#pragma unroll
            for (int kk = 0; kk < 8; ++kk) {
                const float* base = Qs + (wq + g) * 68 + kk * 8 + 2 * q4;
                float2 lo = *(const float2*)base;
                float2 hi = *(const float2*)(base + 8 * 68);
                qf[kk][0] = __float_as_uint(lo.x);
                qf[kk][1] = __float_as_uint(hi.x);
                qf[kk][2] = __float_as_uint(lo.y);
                qf[kk][3] = __float_as_uint(hi.y);
            }
        }
        const float* Kc = Ks + (it & 1) * (32 * 68);
        const float* Vc = Vs + (it & 1) * (32 * 72);

        // ---- scores: S(16x32) = Q K^T ----
        float s[4][4] = {};
#pragma unroll
        for (int kk = 0; kk < 8; ++kk) {
#pragma unroll
            for (int nt = 0; nt < 4; ++nt) {
                float2 bb = *(const float2*)(Kc + (nt * 8 + g) * 68 + kk * 8 + 2 * q4);
                uint32_t bf[2] = { __float_as_uint(bb.x), __float_as_uint(bb.y) };
                mma8(s[nt], qf[kk], bf);
            }
        }

        // ---- online softmax ----
        float mx0 = -1e30f, mx1 = -1e30f;
#pragma unroll
        for (int nt = 0; nt < 4; ++nt) {
            mx0 = fmaxf(mx0, fmaxf(s[nt][0], s[nt][1]));
            mx1 = fmaxf(mx1, fmaxf(s[nt][2], s[nt][3]));
        }
        mx0 = fmaxf(mx0, __shfl_xor_sync(0xffffffffu, mx0, 1));
        mx0 = fmaxf(mx0, __shfl_xor_sync(0xffffffffu, mx0, 2));
        mx1 = fmaxf(mx1, __shfl_xor_sync(0xffffffffu, mx1, 1));
        mx1 = fmaxf(mx1, __shfl_xor_sync(0xffffffffu, mx1, 2));

        float mn0 = fmaxf(m0, mx0), mn1 = fmaxf(m1, mx1);
        float al0 = fexp2(CE * (m0 - mn0)), al1 = fexp2(CE * (m1 - mn1));
        m0 = mn0; m1 = mn1;

        float sum0 = 0.f, sum1 = 0.f;
#pragma unroll
        for (int nt = 0; nt < 4; ++nt) {
            s[nt][0] = fexp2(CE * (s[nt][0] - m0));
            s[nt][1] = fexp2(CE * (s[nt][1] - m0));
            s[nt][2] = fexp2(CE * (s[nt][2] - m1));
            s[nt][3] = fexp2(CE * (s[nt][3] - m1));
            sum0 += s[nt][0] + s[nt][1];
            sum1 += s[nt][2] + s[nt][3];
        }
        sum0 += __shfl_xor_sync(0xffffffffu, sum0, 1);
        sum0 += __shfl_xor_sync(0xffffffffu, sum0, 2);
        sum1 += __shfl_xor_sync(0xffffffffu, sum1, 1);
        sum1 += __shfl_xor_sync(0xffffffffu, sum1, 2);
        l0 = l0 * al0 + sum0;
        l1 = l1 * al1 + sum1;
#pragma unroll
        for (int dt = 0; dt < 8; ++dt) {
            o[dt][0] *= al0; o[dt][1] *= al0; o[dt][2] *= al1; o[dt][3] *= al1;
        }

        // ---- PV: O += P V ----
#pragma unroll
        for (int kt = 0; kt < 4; ++kt) {
            uint32_t pa[4];
            cfrag_to_afrag(s[kt], pa);
#pragma unroll
            for (int dt = 0; dt < 8; ++dt) {
                uint32_t bf[2];
                const float* base = Vc + (kt * 8 + q4) * 72 + dt * 8 + g;
                bf[0] = __float_as_uint(base[0]);
                bf[1] = __float_as_uint(base[4 * 72]);
                mma8(o[dt], pa, bf);
            }
        }
        __syncthreads();
    }

    // ---- epilogue: normalize + tf32 + COLUMN-PERMUTED write for proj ----
    const float inv0 = 1.0f / l0, inv1 = 1.0f / l1;
    const int b = bh >> 4, h = bh & 15;
    const int r0 = q0 + wq + g, r1 = r0 + 8;
    const int p0 = ((q4 & 1) << 2) | (q4 >> 1);        // p(2q4); p(2q4+1)=p0+2
    float* O0 = g_attn + ((size_t)(b * S_LEN) + r0) * H_DIM + h * HD;
    float* O1 = g_attn + ((size_t)(b * S_LEN) + r1) * H_DIM + h * HD;
#pragma unroll
    for (int dt = 0; dt < 8; ++dt) {
        int c = dt * 8 + p0;
        O0[c]     = f2tf32f(o[dt][0] * inv0);
        O0[c + 2] = f2tf32f(o[dt][1] * inv0);
        O1[c]     = f2tf32f(o[dt][2] * inv1);
        O1[c + 2] = f2tf32f(o[dt][3] * inv1);
    }
}

// ================= launch =================
extern "C" void kernel_launch(void* const* d_in, const int* in_sizes, int n_in,
                              void* d_out, int out_size)
{
    const float* x     = (const float*)d_in[0];   // [2,2048,1024]
    const float* Wqkv  = (const float*)d_in[1];   // [3072,1024]
    const float* Wproj = (const float*)d_in[2];   // [1024,1024]
    float* out = (float*)d_out;                   // [2,2048,1024]

    const int GEMM_SMEM  = 2 * 2 * 128 * 36 * 4;                       // 73728
    const int FLASH_SMEM = (128 * 68 + 2 * 32 * 68 + 2 * 32 * 72) * 4; // 70656
    cudaFuncSetAttribute(gemm_qkv,  cudaFuncAttributeMaxDynamicSharedMemorySize, GEMM_SMEM);
    cudaFuncSetAttribute(gemm_proj, cudaFuncAttributeMaxDynamicSharedMemorySize, GEMM_SMEM);
    cudaFuncSetAttribute(flash_attn, cudaFuncAttributeMaxDynamicSharedMemorySize, FLASH_SMEM);

    // 5 launches; flash_attn is launch #4 (the one ncu captures).
    prep<<<4352, 256>>>(x, Wqkv, Wproj);
    gemm_qkv<<<dim3(QKV_N / 128, M_ROWS / 128), 256, GEMM_SMEM>>>();
    rope_permute<<<(3 << 22) / 256, 256>>>();
    flash_attn<<<dim3(S_LEN / 128, BH_TOT), 256, FLASH_SMEM>>>();
    gemm_proj<<<dim3(H_DIM / 128, M_ROWS / 128), 256, GEMM_SMEM>>>(out);
}

// round 15
// speedup vs baseline: 1.6089x; 1.0067x over previous
#include <cuda_runtime.h>
#include <math.h>
#include <stdint.h>

// Problem constants
#define S_LEN   2048
#define NH      16
#define HD      64
#define BH_TOT  32          // B * NH
#define M_ROWS  4096        // B * S
#define H_DIM   1024
#define QKV_N   3072

// Contraction-dim permutation (groups of 8): storage [k0,k4,k1,k5,k2,k6,k3,k7].
// Applied to x/Wqkv/Wproj K-dims, Q/K head-dims, g_attn columns.
// mma fragment k-pair (q4, q4+4) becomes adjacent -> float2 loads.

// -------- scratch (device globals: no allocation allowed) --------
__device__ float g_qkv[(size_t)M_ROWS * QKV_N];          // fp32, TRUE col order
__device__ float g_q[(size_t)BH_TOT * S_LEN * HD];       // tf32, d-permuted
__device__ float g_k[(size_t)BH_TOT * S_LEN * HD];       // tf32, d-permuted
__device__ float g_v[(size_t)BH_TOT * S_LEN * HD];       // tf32, TRUE order
__device__ float g_attn[(size_t)M_ROWS * H_DIM];         // tf32, col-permuted
__device__ float g_xa[(size_t)M_ROWS * H_DIM];           // tf32, k-permuted
__device__ float g_wqkv[(size_t)QKV_N * H_DIM];          // tf32, k-permuted
__device__ float g_wproj[(size_t)H_DIM * H_DIM];         // tf32, k-permuted
__device__ float g_cos[S_LEN * 32];
__device__ float g_sin[S_LEN * 32];

// ================= small helpers =================
__device__ __forceinline__ uint32_t f2tf32(float x) {
    uint32_t r; asm("cvt.rna.tf32.f32 %0, %1;" : "=r"(r) : "f"(x)); return r;
}
__device__ __forceinline__ float f2tf32f(float x) { return __uint_as_float(f2tf32(x)); }

__device__ __forceinline__ void mma8(float d[4], const uint32_t a[4], const uint32_t b[2]) {
    asm volatile("mma.sync.aligned.m16n8k8.row.col.f32.tf32.tf32.f32 "
                 "{%0,%1,%2,%3}, {%4,%5,%6,%7}, {%8,%9}, {%0,%1,%2,%3};\n"
                 : "+f"(d[0]), "+f"(d[1]), "+f"(d[2]), "+f"(d[3])
                 : "r"(a[0]), "r"(a[1]), "r"(a[2]), "r"(a[3]),
                   "r"(b[0]), "r"(b[1]));
}

__device__ __forceinline__ void cp16(uint32_t s, const void* g) {
    asm volatile("cp.async.cg.shared.global [%0], [%1], 16;" :: "r"(s), "l"(g));
}
__device__ __forceinline__ void cp_commit() { asm volatile("cp.async.commit_group;"); }
template<int N> __device__ __forceinline__ void cp_wait() {
    asm volatile("cp.async.wait_group %0;" :: "n"(N));
}

// pure-FMA exp2 (degree-6; rel err ~1e-7). No MUFU.
__device__ __forceinline__ float fexp2(float x) {
    x = fmaxf(x, -100.f);
    float i = rintf(x);
    float f = x - i;
    float p = fmaf(f, 1.54035304e-4f, 1.33335581e-3f);
    p = fmaf(p, f, 9.61812911e-3f);
    p = fmaf(p, f, 5.55041087e-2f);
    p = fmaf(p, f, 2.40226507e-1f);
    p = fmaf(p, f, 6.93147181e-1f);
    p = fmaf(p, f, 1.0f);
    return __int_as_float(__float_as_int(p) + (((int)i) << 23));
}

// C-fragment (m16n8 f32) -> A-fragment (m16k8 tf32) of the SAME 16x8 tile.
__device__ __forceinline__ void cfrag_to_afrag(const float c[4], uint32_t a[4]) {
    int t = threadIdx.x & 31;
    int src0 = (t & 28) | ((t & 3) >> 1);
    int src2 = src0 + 2;
    float x00 = __shfl_sync(0xffffffffu, c[0], src0);
    float x01 = __shfl_sync(0xffffffffu, c[1], src0);
    float x10 = __shfl_sync(0xffffffffu, c[2], src0);
    float x11 = __shfl_sync(0xffffffffu, c[3], src0);
    float y00 = __shfl_sync(0xffffffffu, c[0], src2);
    float y01 = __shfl_sync(0xffffffffu, c[1], src2);
    float y10 = __shfl_sync(0xffffffffu, c[2], src2);
    float y11 = __shfl_sync(0xffffffffu, c[3], src2);
    bool odd = t & 1;
    a[0] = f2tf32(odd ? x01 : x00);
    a[1] = f2tf32(odd ? x11 : x10);
    a[2] = f2tf32(odd ? y01 : y00);
    a[3] = f2tf32(odd ? y11 : y10);
}

// ================= fused prep: rope tables + 3x (tf32 round + k-permute) ==
__device__ __forceinline__ void cvt_perm8_body(
    const float* __restrict__ in, float* __restrict__ out, int blk)
{
    int gi = blk * 256 + threadIdx.x;
    const float4* p = (const float4*)(in + (size_t)gi * 8);
    float4 a = p[0], b = p[1];          // a = k0..3, b = k4..7
    float4 o0 = make_float4(f2tf32f(a.x), f2tf32f(b.x), f2tf32f(a.y), f2tf32f(b.y));
    float4 o1 = make_float4(f2tf32f(a.z), f2tf32f(b.z), f2tf32f(a.w), f2tf32f(b.w));
    float4* q = (float4*)(out + (size_t)gi * 8);
    q[0] = o0; q[1] = o1;
}

__global__ void __launch_bounds__(256) prep(
    const float* __restrict__ x, const float* __restrict__ Wqkv,
    const float* __restrict__ Wproj)
{
    int b = blockIdx.x;
    if (b < 2048) {                       // x
        cvt_perm8_body(x, g_xa, b);
    } else if (b < 3584) {                // Wqkv
        cvt_perm8_body(Wqkv, g_wqkv, b - 2048);
    } else if (b < 4096) {                // Wproj
        cvt_perm8_body(Wproj, g_wproj, b - 3584);
    } else {                              // rope tables
        int idx = (b - 4096) * 256 + threadIdx.x;
        int s = idx >> 5, j = idx & 31;
        double invf = exp(-log(10000.0) * (double)j / 32.0);
        double ang  = (double)s * invf;
        g_cos[idx] = (float)cos(ang);
        g_sin[idx] = (float)sin(ang);
    }
}

// ================= tf32 GEMM: C[M][N] = A[M][K] * B[N][K]^T ===============
__device__ __forceinline__ void gemm_body(
    const float* __restrict__ A, const float* __restrict__ B,
    float* __restrict__ C, int M, int N, int K)
{
    extern __shared__ float sm[];
    float* As = sm;
    float* Bs = sm + 2 * 128 * 36;

    const int tid = threadIdx.x;
    const int bm = blockIdx.y * 128, bn = blockIdx.x * 128;

    const int lr = tid >> 1;
    const int k0 = (tid & 1) << 4;
    const float* Ag = A + (size_t)(bm + lr) * K + k0;
    const float* Bg = B + (size_t)(bn + lr) * K + k0;
    uint32_t sA = (uint32_t)__cvta_generic_to_shared(As) + (lr * 36 + k0) * 4;
    uint32_t sB = (uint32_t)__cvta_generic_to_shared(Bs) + (lr * 36 + k0) * 4;
    const uint32_t bufB = 128 * 36 * 4;

    auto issue = [&](int chunk) {
        int buf = chunk & 1;
        const float* a = Ag + chunk * 32;
        const float* b = Bg + chunk * 32;
        uint32_t da = sA + buf * bufB;
        uint32_t db = sB + buf * bufB;
#pragma unroll
        for (int j = 0; j < 4; ++j) { cp16(da + j * 16, a + j * 4); cp16(db + j * 16, b + j * 4); }
        cp_commit();
    };

    issue(0);

    const int warp = tid >> 5, lane = tid & 31;
    const int g = lane >> 2, q4 = lane & 3;
    const int wm = (warp >> 1) * 32;
    const int wn = (warp & 1) * 64;

    float acc[2][8][4] = {};
    const int nChunks = K >> 5;
    for (int it = 0; it < nChunks; ++it) {
        if (it + 1 < nChunks) { issue(it + 1); cp_wait<1>(); }
        else                  { cp_wait<0>(); }
        __syncthreads();
        const float* Ab = As + (it & 1) * (128 * 36);
        const float* Bb = Bs + (it & 1) * (128 * 36);
#pragma unroll
        for (int kk = 0; kk < 4; ++kk) {
            uint32_t af[2][4];
#pragma unroll
            for (int mi = 0; mi < 2; ++mi) {
                const float* base = Ab + (wm + mi * 16 + g) * 36 + kk * 8 + 2 * q4;
                float2 lo = *(const float2*)base;
                float2 hi = *(const float2*)(base + 8 * 36);
                af[mi][0] = __float_as_uint(lo.x);
                af[mi][1] = __float_as_uint(hi.x);
                af[mi][2] = __float_as_uint(lo.y);
                af[mi][3] = __float_as_uint(hi.y);
            }
#pragma unroll
            for (int j = 0; j < 8; ++j) {
                float2 bb = *(const float2*)(Bb + (wn + j * 8 + g) * 36 + kk * 8 + 2 * q4);
                uint32_t bf[2] = { __float_as_uint(bb.x), __float_as_uint(bb.y) };
                mma8(acc[0][j], af[0], bf);
                mma8(acc[1][j], af[1], bf);
            }
        }
        __syncthreads();
    }

#pragma unroll
    for (int mi = 0; mi < 2; ++mi)
#pragma unroll
        for (int r = 0; r < 2; ++r) {
            int row = bm + wm + mi * 16 + g + r * 8;
            float* Cp = C + (size_t)row * N + bn + wn;
#pragma unroll
            for (int j = 0; j < 8; ++j) {
                float2 v = make_float2(acc[mi][j][r * 2], acc[mi][j][r * 2 + 1]);
                *(float2*)(Cp + j * 8 + q4 * 2) = v;
            }
        }
}

__global__ void __launch_bounds__(256, 2) gemm_qkv() {
    gemm_body(g_xa, g_wqkv, g_qkv, M_ROWS, QKV_N, H_DIM);
}
__global__ void __launch_bounds__(256, 2) gemm_proj(float* __restrict__ out) {
    gemm_body(g_attn, g_wproj, out, M_ROWS, H_DIM, H_DIM);
}

// ================= RoPE + head-permute (tf32; Q/K d-permuted) ============
__global__ void __launch_bounds__(256) rope_permute() {
    int idx = blockIdx.x * blockDim.x + threadIdx.x;
    if (idx >= (3 << 22)) return;
    const int pos    = idx & 63;
    const int s      = (idx >> 6) & 2047;
    const int bh     = (idx >> 17) & 31;
    const int region = idx >> 22;                       // 0=q 1=k 2=v
    const int b = bh >> 4, h = bh & 15;
    const int m = b * S_LEN + s;

    const float* src = g_qkv + (size_t)m * QKV_N + region * H_DIM + h * HD;
    float val;
    if (region == 2) {
        val = src[pos];
    } else {
        int low = pos & 7;
        int d = (pos & ~7) | ((low >> 1) | ((low & 1) << 2));   // true d
        if (d >= 32) {
            val = src[d];
        } else {
            const float c  = g_cos[s * 32 + d];
            const float sn = g_sin[s * 32 + d];
            const float x0 = src[d];
            const float xr = (d < 16) ? -src[d + 16] : src[d - 16];
            val = fmaf(x0, c, xr * sn);
        }
    }
    float* dst = (region == 0) ? g_q : (region == 1) ? g_k : g_v;
    dst[((size_t)bh * S_LEN + s) * HD + pos] = f2tf32f(val);
}

// ================= Flash attention (tf32 mma, FMA softmax) ===============
// CTA: 128 Q rows x bh. 8 warps; warp owns 16 Q rows.  KV chunks of 32,
// 4-buffer cp.async ring, ONE __syncthreads per chunk.  Q gmem->regs.
// smem = (4*32*68 + 4*32*72) * 4 = 71680 B; 2 CTAs/SM (regs <=128).
#define FCHUNK 32
__global__ void __launch_bounds__(256, 2) flash_attn() {
    extern __shared__ float sm[];
    float* Ks = sm;                        // 4 buf x 32x68
    float* Vs = sm + 4 * 32 * 68;          // 4 buf x 32x72

    const int tid = threadIdx.x;
    const int warp = tid >> 5, lane = tid & 31;
    const int g = lane >> 2, q4 = lane & 3;
    const int q0 = blockIdx.x * 128;
    const int bh = blockIdx.y;

    const float* Qg = g_q + ((size_t)bh * S_LEN + q0) * HD;
    const float* Kb = g_k + (size_t)bh * S_LEN * HD;
    const float* Vb = g_v + (size_t)bh * S_LEN * HD;

    const int kc = tid >> 3;               // 0..31 row
    const int kd = (tid & 7) * 8;          // col block of 8
    uint32_t sK = (uint32_t)__cvta_generic_to_shared(Ks) + (kc * 68 + kd) * 4;
    uint32_t sV = (uint32_t)__cvta_generic_to_shared(Vs) + (kc * 72 + kd) * 4;
    auto issueKV = [&](int chunk) {
        int buf = chunk & 3;
        const float* kg = Kb + (size_t)chunk * FCHUNK * 64 + kc * 64 + kd;
        const float* vg = Vb + (size_t)chunk * FCHUNK * 64 + kc * 64 + kd;
        uint32_t dk = sK + buf * (32 * 68 * 4);
        uint32_t dv = sV + buf * (32 * 72 * 4);
#pragma unroll
        for (int j = 0; j < 2; ++j) { cp16(dk + j * 16, kg + j * 4); cp16(dv + j * 16, vg + j * 4); }
        cp_commit();
    };
    issueKV(0); issueKV(1); issueKV(2);    // ring prefill (3 in flight)

    // Q: gmem -> registers directly (one-time; 32B-segment coalescing)
    const int wq = warp * 16;
    uint32_t qf[8][4];
#pragma unroll
    for (int kk = 0; kk < 8; ++kk) {
        const float* base = Qg + (wq + g) * 64 + kk * 8 + 2 * q4;
        float2 lo = *(const float2*)base;
        float2 hi = *(const float2*)(base + 8 * 64);
        qf[kk][0] = __float_as_uint(lo.x);
        qf[kk][1] = __float_as_uint(hi.x);
        qf[kk][2] = __float_as_uint(lo.y);
        qf[kk][3] = __float_as_uint(hi.y);
    }

    float o[8][4] = {};
    float m0 = -1e30f, m1 = -1e30f, l0 = 0.f, l1 = 0.f;
    const float CE = 0.125f * 1.44269504088896f;   // scale * log2(e)

    const int nChunks = S_LEN / FCHUNK;    // 64
    for (int it = 0; it < nChunks; ++it) {
        cp_wait<2>();          // chunk it complete (2 younger groups may pend)
        __syncthreads();       // (a) all threads' chunk-it data visible
                               // (b) all warps left buffer (it+3)&3 (used at it-1)
        if (it + 3 < nChunks) issueKV(it + 3);

        const float* Kc = Ks + (it & 3) * (32 * 68);
        const float* Vc = Vs + (it & 3) * (32 * 72);

        // ---- scores: S(16x32) = Q K^T ----
        float s[4][4] = {};
#pragma unroll
        for (int kk = 0; kk < 8; ++kk) {
#pragma unroll
            for (int nt = 0; nt < 4; ++nt) {
                float2 bb = *(const float2*)(Kc + (nt * 8 + g) * 68 + kk * 8 + 2 * q4);
                uint32_t bf[2] = { __float_as_uint(bb.x), __float_as_uint(bb.y) };
                mma8(s[nt], qf[kk], bf);
            }
        }

        // ---- online softmax ----
        float mx0 = -1e30f, mx1 = -1e30f;
#pragma unroll
        for (int nt = 0; nt < 4; ++nt) {
            mx0 = fmaxf(mx0, fmaxf(s[nt][0], s[nt][1]));
            mx1 = fmaxf(mx1, fmaxf(s[nt][2], s[nt][3]));
        }
        mx0 = fmaxf(mx0, __shfl_xor_sync(0xffffffffu, mx0, 1));
        mx0 = fmaxf(mx0, __shfl_xor_sync(0xffffffffu, mx0, 2));
        mx1 = fmaxf(mx1, __shfl_xor_sync(0xffffffffu, mx1, 1));
        mx1 = fmaxf(mx1, __shfl_xor_sync(0xffffffffu, mx1, 2));

        float mn0 = fmaxf(m0, mx0), mn1 = fmaxf(m1, mx1);
        float al0 = fexp2(CE * (m0 - mn0)), al1 = fexp2(CE * (m1 - mn1));
        m0 = mn0; m1 = mn1;

        float sum0 = 0.f, sum1 = 0.f;
#pragma unroll
        for (int nt = 0; nt < 4; ++nt) {
            s[nt][0] = fexp2(CE * (s[nt][0] - m0));
            s[nt][1] = fexp2(CE * (s[nt][1] - m0));
            s[nt][2] = fexp2(CE * (s[nt][2] - m1));
            s[nt][3] = fexp2(CE * (s[nt][3] - m1));
            sum0 += s[nt][0] + s[nt][1];
            sum1 += s[nt][2] + s[nt][3];
        }
        sum0 += __shfl_xor_sync(0xffffffffu, sum0, 1);
        sum0 += __shfl_xor_sync(0xffffffffu, sum0, 2);
        sum1 += __shfl_xor_sync(0xffffffffu, sum1, 1);
        sum1 += __shfl_xor_sync(0xffffffffu, sum1, 2);
        l0 = l0 * al0 + sum0;
        l1 = l1 * al1 + sum1;
#pragma unroll
        for (int dt = 0; dt < 8; ++dt) {
            o[dt][0] *= al0; o[dt][1] *= al0; o[dt][2] *= al1; o[dt][3] *= al1;
        }

        // ---- PV: O += P V ----
#pragma unroll
        for (int kt = 0; kt < 4; ++kt) {
            uint32_t pa[4];
            cfrag_to_afrag(s[kt], pa);
#pragma unroll
            for (int dt = 0; dt < 8; ++dt) {
                uint32_t bf[2];
                const float* base = Vc + (kt * 8 + q4) * 72 + dt * 8 + g;
                bf[0] = __float_as_uint(base[0]);
                bf[1] = __float_as_uint(base[4 * 72]);
                mma8(o[dt], pa, bf);
            }
        }
        // no trailing barrier: next iteration's barrier protects buffer reuse
    }

    // ---- epilogue: normalize + tf32 + COLUMN-PERMUTED write for proj ----
    const float inv0 = 1.0f / l0, inv1 = 1.0f / l1;
    const int b = bh >> 4, h = bh & 15;
    const int r0 = q0 + wq + g, r1 = r0 + 8;
    const int p0 = ((q4 & 1) << 2) | (q4 >> 1);        // p(2q4); p(2q4+1)=p0+2
    float* O0 = g_attn + ((size_t)(b * S_LEN) + r0) * H_DIM + h * HD;
    float* O1 = g_attn + ((size_t)(b * S_LEN) + r1) * H_DIM + h * HD;
#pragma unroll
    for (int dt = 0; dt < 8; ++dt) {
        int c = dt * 8 + p0;
        O0[c]     = f2tf32f(o[dt][0] * inv0);
        O0[c + 2] = f2tf32f(o[dt][1] * inv0);
        O1[c]     = f2tf32f(o[dt][2] * inv1);
        O1[c + 2] = f2tf32f(o[dt][3] * inv1);
    }
}

// ================= launch =================
extern "C" void kernel_launch(void* const* d_in, const int* in_sizes, int n_in,
                              void* d_out, int out_size)
{
    const float* x     = (const float*)d_in[0];   // [2,2048,1024]
    const float* Wqkv  = (const float*)d_in[1];   // [3072,1024]
    const float* Wproj = (const float*)d_in[2];   // [1024,1024]
    float* out = (float*)d_out;                   // [2,2048,1024]

    const int GEMM_SMEM  = 2 * 2 * 128 * 36 * 4;                 // 73728
    const int FLASH_SMEM = (4 * 32 * 68 + 4 * 32 * 72) * 4;      // 71680
    cudaFuncSetAttribute(gemm_qkv,  cudaFuncAttributeMaxDynamicSharedMemorySize, GEMM_SMEM);
    cudaFuncSetAttribute(gemm_proj, cudaFuncAttributeMaxDynamicSharedMemorySize, GEMM_SMEM);
    cudaFuncSetAttribute(flash_attn, cudaFuncAttributeMaxDynamicSharedMemorySize, FLASH_SMEM);

    // 5 launches; flash_attn is launch #4 (the one ncu captures).
    prep<<<4352, 256>>>(x, Wqkv, Wproj);
    gemm_qkv<<<dim3(QKV_N / 128, M_ROWS / 128), 256, GEMM_SMEM>>>();
    rope_permute<<<(3 << 22) / 256, 256>>>();
    flash_attn<<<dim3(S_LEN / 128, BH_TOT), 256, FLASH_SMEM>>>();
    gemm_proj<<<dim3(H_DIM / 128, M_ROWS / 128), 256, GEMM_SMEM>>>(out);
}